// round 11
// baseline (speedup 1.0000x reference)
#include <cuda_runtime.h>
#include <cstdint>

#define NRES 4096
#define KNB  48
#define EDIM 128
#define DFEAT 416
#define NEDGE (NRES*KNB)   // 196608
#define NC1 13
#define NC2 4
#define TILE 64            // edges per CTA

typedef unsigned int uint;
typedef unsigned long long ull;

// ---------------- device-global scratch ----------------
__device__ float g_bb[NRES * 15];
__device__ float g_ca[NRES * 3];
__device__ int   g_idx[NEDGE];
// bf16 2-split weights, pre-packed in m16n8k16 B-fragment layout (L2-resident).
__device__ __align__(16) uint g_B1hi[NC1 * 2048];
__device__ __align__(16) uint g_B1lo[NC1 * 2048];
__device__ __align__(16) uint g_B2hi[NC2 * 2048];
__device__ __align__(16) uint g_B2lo[NC2 * 2048];
__device__ float g_pbfold[EDIM];

// ---------------- helpers ----------------
__device__ __forceinline__ uint32_t smaddr(const void* p) {
    return (uint32_t)__cvta_generic_to_shared(p);
}
#define LDMX4(r, addr) \
    asm volatile("ldmatrix.sync.aligned.m8n8.x4.shared.b16 {%0,%1,%2,%3}, [%4];" \
        : "=r"((r)[0]), "=r"((r)[1]), "=r"((r)[2]), "=r"((r)[3]) : "r"(addr))

// split float2 into packed bf16x2 hi + residual bf16x2 lo (v.x -> low half)
__device__ __forceinline__ void bfsplit(float2 v, uint& h, uint& l) {
    asm("cvt.rn.bf16x2.f32 %0, %1, %2;" : "=r"(h) : "f"(v.y), "f"(v.x));
    float f0 = __uint_as_float(h << 16);
    float f1 = __uint_as_float(h & 0xffff0000u);
    asm("cvt.rn.bf16x2.f32 %0, %1, %2;" : "=r"(l) : "f"(v.y - f1), "f"(v.x - f0));
}

__device__ __forceinline__ void mma16(float* d, const uint* a, uint b0, uint b1) {
    asm volatile(
        "mma.sync.aligned.m16n8k16.row.col.f32.bf16.bf16.f32 "
        "{%0,%1,%2,%3}, {%4,%5,%6,%7}, {%8,%9}, {%0,%1,%2,%3};"
        : "+f"(d[0]), "+f"(d[1]), "+f"(d[2]), "+f"(d[3])
        : "r"(a[0]), "r"(a[1]), "r"(a[2]), "r"(a[3]), "r"(b0), "r"(b1));
}

// exp(x), x<=0, pure FMA pipe
__device__ __forceinline__ float fexp(float x) {
    x = fmaxf(x, -87.0f);
    float y  = x * 1.4426950408889634f;
    float z  = y + 12582912.0f;
    float nf = z - 12582912.0f;
    float g  = (y - nf) * 0.6931471805599453f;
    float p  = fmaf(g, 1.0f/720.0f, 1.0f/120.0f);
    p = fmaf(g, p, 1.0f/24.0f);
    p = fmaf(g, p, 1.0f/6.0f);
    p = fmaf(g, p, 0.5f);
    p = fmaf(g, p, 1.0f);
    p = fmaf(g, p, 1.0f);
    int n = __float_as_int(z) - 0x4B400000;
    return __int_as_float((n + 127) << 23) * p;
}

// ---------------- kernel 1: backbone ----------------
__global__ void k_backbone(const float* __restrict__ coords) {
    int i = blockIdx.x * blockDim.x + threadIdx.x;
    if (i >= NRES) return;
    const float* p = coords + i * 12;
    float n0=p[0],n1=p[1],n2=p[2];
    float a0=p[3],a1=p[4],a2=p[5];
    float c0=p[6],c1=p[7],c2=p[8];
    float o0=p[9],o1=p[10],o2=p[11];
    float b0=a0-n0, b1=a1-n1, b2=a2-n2;
    float d0=c0-a0, d1=c1-a1, d2=c2-a2;
    float x0 = b1*d2 - b2*d1;
    float x1 = b2*d0 - b0*d2;
    float x2 = b0*d1 - b1*d0;
    float cb0 = -0.58273431f*x0 + 0.56802827f*b0 - 0.54067466f*d0 + a0;
    float cb1 = -0.58273431f*x1 + 0.56802827f*b1 - 0.54067466f*d1 + a1;
    float cb2 = -0.58273431f*x2 + 0.56802827f*b2 - 0.54067466f*d2 + a2;
    float* q = g_bb + i * 15;
    q[0]=n0; q[1]=n1; q[2]=n2;
    q[3]=a0; q[4]=a1; q[5]=a2;
    q[6]=c0; q[7]=c1; q[8]=c2;
    q[9]=o0; q[10]=o1; q[11]=o2;
    q[12]=cb0; q[13]=cb1; q[14]=cb2;
    g_ca[i] = a0; g_ca[NRES + i] = a1; g_ca[2*NRES + i] = a2;
}

// ---------------- kernel 2: exact 48-NN (parallel threshold scan) ----------------
__global__ __launch_bounds__(256) void k_topk(const float* __restrict__ mask,
                                              float* __restrict__ out_idx) {
    __shared__ float se[NRES];
    __shared__ uint  hist[1024];
    __shared__ ull   cand[2048];
    __shared__ uint  wsum[8];
    __shared__ int   s_thr, s_cnt;
    int i = blockIdx.x, tid = threadIdx.x;
    int lane = tid & 31, wid = tid >> 5;

    for (int b = tid; b < 1024; b += 256) hist[b] = 0;
    if (tid == 0) s_cnt = 0;
    float cax = g_ca[i], cay = g_ca[NRES + i], caz = g_ca[2*NRES + i];
    float mi = mask[i];
    __syncthreads();

    for (int j = tid; j < NRES; j += 256) {
        float dx = __fsub_rn(cax, g_ca[j]);
        float dy = __fsub_rn(cay, g_ca[NRES + j]);
        float dz = __fsub_rn(caz, g_ca[2*NRES + j]);
        float d2 = __fadd_rn(__fadd_rn(__fmul_rn(dx,dx), __fmul_rn(dy,dy)), __fmul_rn(dz,dz));
        float e  = __fadd_rn(d2, 1e-6f);
        if (__fmul_rn(mi, mask[j]) == 0.0f) e = __int_as_float(0x7f800000);
        se[j] = e;
        atomicAdd(&hist[__float_as_uint(e) >> 21], 1u);
    }
    __syncthreads();

    {
        int b0 = tid * 4;
        uint s4 = hist[b0] + hist[b0+1] + hist[b0+2] + hist[b0+3];
        uint v = s4;
        #pragma unroll
        for (int off = 1; off < 32; off <<= 1) {
            uint o = __shfl_up_sync(0xffffffffu, v, off);
            if (lane >= off) v += o;
        }
        if (lane == 31) wsum[wid] = v;
        __syncthreads();
        uint basec = 0;
        #pragma unroll
        for (int w = 0; w < 8; w++) if (w < wid) basec += wsum[w];
        uint incl = basec + v;
        uint excl = incl - s4;
        if (excl < KNB && KNB <= incl) {
            uint cum = excl; int b = b0;
            while (cum + hist[b] < KNB) { cum += hist[b]; b++; }
            s_thr = b;
        }
    }
    __syncthreads();
    uint B = (uint)s_thr;

    for (int j = tid; j < NRES; j += 256) {
        float e = se[j];
        if ((__float_as_uint(e) >> 21) <= B) {
            int p = atomicAdd(&s_cnt, 1);
            if (p < 2048) {
                float dist = __fsqrt_rn(e);
                cand[p] = ((ull)__float_as_uint(dist) << 32) | (uint)j;
            }
        }
    }
    __syncthreads();

    int C = min(s_cnt, 2048);
    int P = 64; while (P < C) P <<= 1;
    for (int p = C + tid; p < P; p += 256) cand[p] = ~0ULL;
    __syncthreads();

    for (int k = 2; k <= P; k <<= 1)
        for (int j2 = k >> 1; j2 > 0; j2 >>= 1) {
            for (int n = tid; n < P; n += 256) {
                int ixj = n ^ j2;
                if (ixj > n) {
                    ull a = cand[n], c2 = cand[ixj];
                    bool up = ((n & k) == 0);
                    if ((a > c2) == up) { cand[n] = c2; cand[ixj] = a; }
                }
            }
            __syncthreads();
        }

    if (tid < KNB) {
        int j = (int)(cand[tid] & 0xffffffffu);
        g_idx[i * KNB + tid] = j;
        if (out_idx) out_idx[i * KNB + tid] = (float)j;
    }
}

// ---------------- kernel 3: weight prep ----------------
__global__ __launch_bounds__(256) void k_prep(const float* __restrict__ wew,
                                              const float* __restrict__ pw,
                                              const float* __restrict__ lnw,
                                              const float* __restrict__ lnb,
                                              const float* __restrict__ pb) {
    int t = blockIdx.x * 256 + threadIdx.x;
    const int NB1 = NC1 * 1024;
    const int NB2 = NC2 * 1024;
    if (t < NB1) {
        int lane = t & 31, ks = (t >> 5) & 1, nt = (t >> 6) & 15, c = t >> 10;
        int g = lane >> 2, tt = lane & 3;
        int n = nt * 8 + g;
        int k = c * 32 + ks * 16 + 2 * tt;
        const float* src = wew + n * DFEAT;
        uint h0, l0, h1, l1;
        bfsplit(make_float2(src[k],     src[k + 1]), h0, l0);
        bfsplit(make_float2(src[k + 8], src[k + 9]), h1, l1);
        ((uint2*)g_B1hi)[t] = make_uint2(h0, h1);
        ((uint2*)g_B1lo)[t] = make_uint2(l0, l1);
    } else if (t < NB1 + NB2) {
        int t2 = t - NB1;
        int lane = t2 & 31, ks = (t2 >> 5) & 1, nt = (t2 >> 6) & 15, c = t2 >> 10;
        int g = lane >> 2, tt = lane & 3;
        int n = nt * 8 + g;
        int k = c * 32 + ks * 16 + 2 * tt;
        const float* src = pw + n * EDIM;
        uint h0, l0, h1, l1;
        bfsplit(make_float2(src[k] * lnw[k],         src[k + 1] * lnw[k + 1]), h0, l0);
        bfsplit(make_float2(src[k + 8] * lnw[k + 8], src[k + 9] * lnw[k + 9]), h1, l1);
        ((uint2*)g_B2hi)[t2] = make_uint2(h0, h1);
        ((uint2*)g_B2lo)[t2] = make_uint2(l0, l1);
    } else if (t < NB1 + NB2 + EDIM) {
        int f = t - NB1 - NB2;
        float s = pb[f];
        for (int k = 0; k < EDIM; k++) s += pw[f * EDIM + k] * lnb[k];
        g_pbfold[f] = s;
    }
}

// ---------------- kernel 4: fused, 64-edge tiles, ALL B via L2 __ldg ----------------
// smem (bytes):
//   union [0, 34816):
//     GEMM1 phase: A stage 2 buf x (hi 64x40 bf16 + lo) = 20480 | spd @20480 (6656) | swp @27136 (2240)
//     LN->GEMM2:   A2hi @0 (17408), A2lo @17408 (17408)
//     epilogue:    stash 64x132 f @0 (33792)
//   sRed @34816: 2048
#define OFF_SPD  20480
#define OFF_SWP  27136
#define OFF_A2L  17408
#define OFF_RED  34816
#define SM_TOT   36864

__global__ void __launch_bounds__(256, 4) k_fused(
    const int* __restrict__ ri, const int* __restrict__ ci,
    const float* __restrict__ wpw, const float* __restrict__ wpb,
    float* __restrict__ out)
{
    extern __shared__ char smb[];
    float* spd = (float*)(smb + OFF_SPD);
    float* swp = (float*)(smb + OFF_SWP);
    float2* sRed = (float2*)(smb + OFF_RED);

    int tid = threadIdx.x, lane = tid & 31, warp = tid >> 5;
    int g = lane >> 2, tt = lane & 3;
    int mh = warp & 1, nh = warp >> 1;          // 2 x 4 warp grid
    int ldrow = (lane & 7) + ((lane >> 3) & 1) * 8;
    int ldcol = ((lane >> 4) & 1) * 16;
    int e0 = blockIdx.x * TILE;

    // ---- prelude ----
    int er = tid >> 2, q = tid & 3;
    int eg = e0 + er;
    int ii = eg / KNB;
    int jj = g_idx[eg];
    for (int p = tid; p < 560; p += 256)
        swp[p] = (p < 544) ? wpw[p] : wpb[p - 544];
    for (int p = tid; p < TILE * 25; p += 256) {
        int e = p / 25, pr = p - e * 25;
        int a = pr / 5, b2 = pr - a * 5;
        int ie = (e0 + e) / KNB;
        int je = g_idx[e0 + e];
        const float* bi = g_bb + ie * 15 + a * 3;
        const float* bj = g_bb + je * 15 + b2 * 3;
        float dx = bi[0] - bj[0], dy = bi[1] - bj[1], dz = bi[2] - bj[2];
        spd[e * 26 + pr] = __fsqrt_rn(dx*dx + dy*dy + dz*dz + 1e-6f);
    }
    int enc;
    {
        int ro = ri[ii] - ri[jj];
        enc = (ci[ii] == ci[jj]) ? min(max(ro + 16, 0), 32) : 33;
    }
    __syncthreads();   // publish spd/swp before any fillA reads

    auto fillA = [&](int c, int b) {
        float v[8];
        if (c == 0 && q < 2) {
            #pragma unroll
            for (int j = 0; j < 8; j++) {
                int f = q * 8 + j;
                v[j] = swp[f * 34 + enc] + swp[544 + f];
            }
        } else {
            int pdIdx = 2 * c - 1 + (q >> 1);
            float pd = spd[er * 26 + pdIdx];
            int binBase = (q & 1) * 8;
            #pragma unroll
            for (int j = 0; j < 8; j++) {
                float t = (pd - (2.0f + 1.3333334f * (float)(binBase + j))) * 0.8f;
                v[j] = fexp(-t * t);
            }
        }
        uint h[4], l[4];
        #pragma unroll
        for (int k = 0; k < 4; k++)
            bfsplit(make_float2(v[2*k], v[2*k+1]), h[k], l[k]);
        char* ph = smb + b * 10240 + er * 80 + q * 16;
        *(uint4*)ph          = make_uint4(h[0], h[1], h[2], h[3]);
        *(uint4*)(ph + 5120) = make_uint4(l[0], l[1], l[2], l[3]);
    };

    float acc[2][4][4];
    #pragma unroll
    for (int mt = 0; mt < 2; mt++)
        #pragma unroll
        for (int nt = 0; nt < 4; nt++)
            #pragma unroll
            for (int z = 0; z < 4; z++) acc[mt][nt][z] = 0.0f;

    // ================= GEMM1: A staged in smem, B streamed from L2 =================
    fillA(0, 0);
    for (int c = 0; c < NC1; c++) {
        int b = c & 1;
        __syncthreads();   // publishes fillA(c); fences prior readers of b^1

        const uint2* bp1h = (const uint2*)g_B1hi + c * 1024;
        const uint2* bp1l = (const uint2*)g_B1lo + c * 1024;
        #pragma unroll
        for (int ks = 0; ks < 2; ks++) {
            uint fh[2][4], fl[2][4];
            #pragma unroll
            for (int mt = 0; mt < 2; mt++) {
                uint ad = smaddr(smb) + b * 10240
                        + (mh * 32 + mt * 16 + ldrow) * 80 + ks * 32 + ldcol;
                LDMX4(fh[mt], ad);
                LDMX4(fl[mt], ad + 5120);
            }
            #pragma unroll
            for (int nt = 0; nt < 4; nt++) {
                int idx = ((nh * 4 + nt) * 2 + ks) * 32 + lane;
                uint2 bh = __ldg(bp1h + idx);
                uint2 bl = __ldg(bp1l + idx);
                #pragma unroll
                for (int mt = 0; mt < 2; mt++) {
                    mma16(acc[mt][nt], fh[mt], bh.x, bh.y);
                    mma16(acc[mt][nt], fh[mt], bl.x, bl.y);
                    mma16(acc[mt][nt], fl[mt], bh.x, bh.y);
                }
            }
        }
        if (c + 1 < NC1) fillA(c + 1, b ^ 1);
    }

    // ================= LayerNorm -> bf16-presplit A2 =================
    {
        float s[2][2], qq[2][2];
        #pragma unroll
        for (int mt = 0; mt < 2; mt++) {
            s[mt][0] = s[mt][1] = qq[mt][0] = qq[mt][1] = 0.f;
            #pragma unroll
            for (int nt = 0; nt < 4; nt++) {
                s[mt][0]  += acc[mt][nt][0] + acc[mt][nt][1];
                qq[mt][0] += acc[mt][nt][0]*acc[mt][nt][0] + acc[mt][nt][1]*acc[mt][nt][1];
                s[mt][1]  += acc[mt][nt][2] + acc[mt][nt][3];
                qq[mt][1] += acc[mt][nt][2]*acc[mt][nt][2] + acc[mt][nt][3]*acc[mt][nt][3];
            }
            #pragma unroll
            for (int off = 1; off <= 2; off <<= 1) {
                s[mt][0]  += __shfl_xor_sync(0xffffffffu, s[mt][0],  off);
                qq[mt][0] += __shfl_xor_sync(0xffffffffu, qq[mt][0], off);
                s[mt][1]  += __shfl_xor_sync(0xffffffffu, s[mt][1],  off);
                qq[mt][1] += __shfl_xor_sync(0xffffffffu, qq[mt][1], off);
            }
        }
        if (tt == 0) {
            #pragma unroll
            for (int mt = 0; mt < 2; mt++)
                #pragma unroll
                for (int rp = 0; rp < 2; rp++) {
                    int r = mh * 32 + mt * 16 + rp * 8 + g;
                    sRed[r * 4 + nh] = make_float2(s[mt][rp], qq[mt][rp]);
                }
        }
        __syncthreads();   // fences last GEMM1 stage reads before A2 overwrite
        float mean[2][2], rstd[2][2];
        #pragma unroll
        for (int mt = 0; mt < 2; mt++)
            #pragma unroll
            for (int rp = 0; rp < 2; rp++) {
                int r = mh * 32 + mt * 16 + rp * 8 + g;
                float S = 0.f, Q = 0.f;
                #pragma unroll
                for (int w = 0; w < 4; w++) {
                    float2 pq = sRed[r * 4 + w];
                    S += pq.x; Q += pq.y;
                }
                float m = S * (1.0f / 128.0f);
                mean[mt][rp] = m;
                rstd[mt][rp] = rsqrtf(Q * (1.0f / 128.0f) - m * m + 1e-5f);
            }
        #pragma unroll
        for (int mt = 0; mt < 2; mt++) {
            int r0 = mh * 32 + mt * 16 + g;
            #pragma unroll
            for (int nt = 0; nt < 4; nt++) {
                int C = nh * 32 + nt * 8 + 2 * tt;
                uint h, l;
                bfsplit(make_float2((acc[mt][nt][0] - mean[mt][0]) * rstd[mt][0],
                                    (acc[mt][nt][1] - mean[mt][0]) * rstd[mt][0]), h, l);
                *(uint*)(smb + r0 * 272 + C * 2)           = h;
                *(uint*)(smb + OFF_A2L + r0 * 272 + C * 2) = l;
                bfsplit(make_float2((acc[mt][nt][2] - mean[mt][1]) * rstd[mt][1],
                                    (acc[mt][nt][3] - mean[mt][1]) * rstd[mt][1]), h, l);
                *(uint*)(smb + (r0 + 8) * 272 + C * 2)           = h;
                *(uint*)(smb + OFF_A2L + (r0 + 8) * 272 + C * 2) = l;
            }
        }
    }
    __syncthreads();

    // ================= GEMM2: A via ldmatrix, B via __ldg =================
    #pragma unroll
    for (int mt = 0; mt < 2; mt++)
        #pragma unroll
        for (int nt = 0; nt < 4; nt++)
            #pragma unroll
            for (int z = 0; z < 4; z++) acc[mt][nt][z] = 0.0f;

    #pragma unroll
    for (int c = 0; c < NC2; c++) {
        #pragma unroll
        for (int ks = 0; ks < 2; ks++) {
            uint fh[2][4], fl[2][4];
            #pragma unroll
            for (int mt = 0; mt < 2; mt++) {
                uint ad = smaddr(smb)
                        + (mh * 32 + mt * 16 + ldrow) * 272 + c * 64 + ks * 32 + ldcol;
                LDMX4(fh[mt], ad);
                LDMX4(fl[mt], ad + OFF_A2L);
            }
            #pragma unroll
            for (int nt = 0; nt < 4; nt++) {
                int idx = c * 1024 + ((nh * 4 + nt) * 2 + ks) * 32 + lane;
                uint2 bh = __ldg((const uint2*)g_B2hi + idx);
                uint2 bl = __ldg((const uint2*)g_B2lo + idx);
                #pragma unroll
                for (int mt = 0; mt < 2; mt++) {
                    mma16(acc[mt][nt], fh[mt], bh.x, bh.y);
                    mma16(acc[mt][nt], fh[mt], bl.x, bl.y);
                    mma16(acc[mt][nt], fl[mt], bh.x, bh.y);
                }
            }
        }
    }

    // ================= epilogue =================
    __syncthreads();   // all A2 reads done before stash overwrite
    {
        float* stash = (float*)smb;
        #pragma unroll
        for (int mt = 0; mt < 2; mt++) {
            int r0 = mh * 32 + mt * 16 + g;
            #pragma unroll
            for (int nt = 0; nt < 4; nt++) {
                int C = nh * 32 + nt * 8 + 2 * tt;
                *(float2*)(stash + r0 * 132 + C)       = make_float2(acc[mt][nt][0], acc[mt][nt][1]);
                *(float2*)(stash + (r0 + 8) * 132 + C) = make_float2(acc[mt][nt][2], acc[mt][nt][3]);
            }
        }
    }
    __syncthreads();
    {
        const float* stash = (const float*)smb;
        int c4 = tid & 31;
        float4 bias = *(const float4*)(g_pbfold + c4 * 4);
        #pragma unroll
        for (int z = 0; z < 8; z++) {
            int idx = tid + 256 * z;
            int row = idx >> 5;
            float4 v = *(const float4*)(stash + row * 132 + c4 * 4);
            v.x += bias.x; v.y += bias.y; v.z += bias.z; v.w += bias.w;
            *(float4*)(out + (long long)(e0 + row) * EDIM + c4 * 4) = v;
        }
    }
}

// ---------------- launch ----------------
extern "C" void kernel_launch(void* const* d_in, const int* in_sizes, int n_in,
                              void* d_out, int out_size) {
    const float* coords = (const float*)d_in[0];
    const float* mask   = (const float*)d_in[1];
    const int*   ri     = (const int*)d_in[2];
    const int*   ci     = (const int*)d_in[3];
    const float* wpw    = (const float*)d_in[4];
    const float* wpb    = (const float*)d_in[5];
    const float* wew    = (const float*)d_in[6];
    const float* lnw    = (const float*)d_in[7];
    const float* lnb    = (const float*)d_in[8];
    const float* pw     = (const float*)d_in[9];
    const float* pb     = (const float*)d_in[10];
    float* out = (float*)d_out;

    long long main_elems = (long long)NEDGE * EDIM;
    float* out_idx = ((long long)out_size > main_elems) ? (out + main_elems) : nullptr;

    cudaFuncSetAttribute(k_fused, cudaFuncAttributeMaxDynamicSharedMemorySize, SM_TOT);

    k_backbone<<<(NRES + 255) / 256, 256>>>(coords);
    k_topk<<<NRES, 256>>>(mask, out_idx);
    k_prep<<<(NC1 * 1024 + NC2 * 1024 + EDIM + 255) / 256, 256>>>(wew, pw, lnw, lnb, pb);
    k_fused<<<NEDGE / TILE, 256, SM_TOT>>>(ri, ci, wpw, wpb, out);
}

// round 12
// speedup vs baseline: 1.5673x; 1.5673x over previous
#include <cuda_runtime.h>
#include <cstdint>

#define NRES 4096
#define KNB  48
#define EDIM 128
#define DFEAT 416
#define NEDGE (NRES*KNB)   // 196608
#define NC1 13
#define NC2 4
#define TILE 64            // edges per CTA

typedef unsigned int uint;
typedef unsigned long long ull;

// ---------------- device-global scratch ----------------
__device__ float g_bb[NRES * 15];
__device__ float g_ca[NRES * 3];
__device__ int   g_idx[NEDGE];
// fp16 weights pre-packed in m16n8k16 B-fragment layout (uint2 per lane entry).
__device__ __align__(16) uint g_B1[NC1 * 2048];
__device__ __align__(16) uint g_B2[NC2 * 2048];
__device__ float g_pbfold[EDIM];

// ---------------- helpers ----------------
__device__ __forceinline__ uint32_t smaddr(const void* p) {
    return (uint32_t)__cvta_generic_to_shared(p);
}
#define CP16(dst, src) \
    asm volatile("cp.async.cg.shared.global [%0], [%1], 16;" :: "r"(dst), "l"(src))
#define CP_COMMIT() asm volatile("cp.async.commit_group;" ::: "memory")
#define CP_WAIT(n)  asm volatile("cp.async.wait_group %0;" :: "n"(n) : "memory")

#define LDMX4(r, addr) \
    asm volatile("ldmatrix.sync.aligned.m8n8.x4.shared.b16 {%0,%1,%2,%3}, [%4];" \
        : "=r"((r)[0]), "=r"((r)[1]), "=r"((r)[2]), "=r"((r)[3]) : "r"(addr))

// pack float2 -> fp16x2 (v.x in low half)
__device__ __forceinline__ uint h2pack(float2 v) {
    uint h;
    asm("cvt.rn.f16x2.f32 %0, %1, %2;" : "=r"(h) : "f"(v.y), "f"(v.x));
    return h;
}

__device__ __forceinline__ void mma16h(float* d, const uint* a, uint b0, uint b1) {
    asm volatile(
        "mma.sync.aligned.m16n8k16.row.col.f32.f16.f16.f32 "
        "{%0,%1,%2,%3}, {%4,%5,%6,%7}, {%8,%9}, {%0,%1,%2,%3};"
        : "+f"(d[0]), "+f"(d[1]), "+f"(d[2]), "+f"(d[3])
        : "r"(a[0]), "r"(a[1]), "r"(a[2]), "r"(a[3]), "r"(b0), "r"(b1));
}

// exp(x), x<=0, pure FMA pipe
__device__ __forceinline__ float fexp(float x) {
    x = fmaxf(x, -87.0f);
    float y  = x * 1.4426950408889634f;
    float z  = y + 12582912.0f;
    float nf = z - 12582912.0f;
    float g  = (y - nf) * 0.6931471805599453f;
    float p  = fmaf(g, 1.0f/720.0f, 1.0f/120.0f);
    p = fmaf(g, p, 1.0f/24.0f);
    p = fmaf(g, p, 1.0f/6.0f);
    p = fmaf(g, p, 0.5f);
    p = fmaf(g, p, 1.0f);
    p = fmaf(g, p, 1.0f);
    int n = __float_as_int(z) - 0x4B400000;
    return __int_as_float((n + 127) << 23) * p;
}

// ---------------- kernel 1: backbone ----------------
__global__ void k_backbone(const float* __restrict__ coords) {
    int i = blockIdx.x * blockDim.x + threadIdx.x;
    if (i >= NRES) return;
    const float* p = coords + i * 12;
    float n0=p[0],n1=p[1],n2=p[2];
    float a0=p[3],a1=p[4],a2=p[5];
    float c0=p[6],c1=p[7],c2=p[8];
    float o0=p[9],o1=p[10],o2=p[11];
    float b0=a0-n0, b1=a1-n1, b2=a2-n2;
    float d0=c0-a0, d1=c1-a1, d2=c2-a2;
    float x0 = b1*d2 - b2*d1;
    float x1 = b2*d0 - b0*d2;
    float x2 = b0*d1 - b1*d0;
    float cb0 = -0.58273431f*x0 + 0.56802827f*b0 - 0.54067466f*d0 + a0;
    float cb1 = -0.58273431f*x1 + 0.56802827f*b1 - 0.54067466f*d1 + a1;
    float cb2 = -0.58273431f*x2 + 0.56802827f*b2 - 0.54067466f*d2 + a2;
    float* q = g_bb + i * 15;
    q[0]=n0; q[1]=n1; q[2]=n2;
    q[3]=a0; q[4]=a1; q[5]=a2;
    q[6]=c0; q[7]=c1; q[8]=c2;
    q[9]=o0; q[10]=o1; q[11]=o2;
    q[12]=cb0; q[13]=cb1; q[14]=cb2;
    g_ca[i] = a0; g_ca[NRES + i] = a1; g_ca[2*NRES + i] = a2;
}

// ---------------- kernel 2: exact 48-NN (parallel threshold scan) ----------------
__global__ __launch_bounds__(256) void k_topk(const float* __restrict__ mask,
                                              float* __restrict__ out_idx) {
    __shared__ float se[NRES];
    __shared__ uint  hist[1024];
    __shared__ ull   cand[2048];
    __shared__ uint  wsum[8];
    __shared__ int   s_thr, s_cnt;
    int i = blockIdx.x, tid = threadIdx.x;
    int lane = tid & 31, wid = tid >> 5;

    for (int b = tid; b < 1024; b += 256) hist[b] = 0;
    if (tid == 0) s_cnt = 0;
    float cax = g_ca[i], cay = g_ca[NRES + i], caz = g_ca[2*NRES + i];
    float mi = mask[i];
    __syncthreads();

    for (int j = tid; j < NRES; j += 256) {
        float dx = __fsub_rn(cax, g_ca[j]);
        float dy = __fsub_rn(cay, g_ca[NRES + j]);
        float dz = __fsub_rn(caz, g_ca[2*NRES + j]);
        float d2 = __fadd_rn(__fadd_rn(__fmul_rn(dx,dx), __fmul_rn(dy,dy)), __fmul_rn(dz,dz));
        float e  = __fadd_rn(d2, 1e-6f);
        if (__fmul_rn(mi, mask[j]) == 0.0f) e = __int_as_float(0x7f800000);
        se[j] = e;
        atomicAdd(&hist[__float_as_uint(e) >> 21], 1u);
    }
    __syncthreads();

    {
        int b0 = tid * 4;
        uint s4 = hist[b0] + hist[b0+1] + hist[b0+2] + hist[b0+3];
        uint v = s4;
        #pragma unroll
        for (int off = 1; off < 32; off <<= 1) {
            uint o = __shfl_up_sync(0xffffffffu, v, off);
            if (lane >= off) v += o;
        }
        if (lane == 31) wsum[wid] = v;
        __syncthreads();
        uint basec = 0;
        #pragma unroll
        for (int w = 0; w < 8; w++) if (w < wid) basec += wsum[w];
        uint incl = basec + v;
        uint excl = incl - s4;
        if (excl < KNB && KNB <= incl) {
            uint cum = excl; int b = b0;
            while (cum + hist[b] < KNB) { cum += hist[b]; b++; }
            s_thr = b;
        }
    }
    __syncthreads();
    uint B = (uint)s_thr;

    for (int j = tid; j < NRES; j += 256) {
        float e = se[j];
        if ((__float_as_uint(e) >> 21) <= B) {
            int p = atomicAdd(&s_cnt, 1);
            if (p < 2048) {
                float dist = __fsqrt_rn(e);
                cand[p] = ((ull)__float_as_uint(dist) << 32) | (uint)j;
            }
        }
    }
    __syncthreads();

    int C = min(s_cnt, 2048);
    int P = 64; while (P < C) P <<= 1;
    for (int p = C + tid; p < P; p += 256) cand[p] = ~0ULL;
    __syncthreads();

    for (int k = 2; k <= P; k <<= 1)
        for (int j2 = k >> 1; j2 > 0; j2 >>= 1) {
            for (int n = tid; n < P; n += 256) {
                int ixj = n ^ j2;
                if (ixj > n) {
                    ull a = cand[n], c2 = cand[ixj];
                    bool up = ((n & k) == 0);
                    if ((a > c2) == up) { cand[n] = c2; cand[ixj] = a; }
                }
            }
            __syncthreads();
        }

    if (tid < KNB) {
        int j = (int)(cand[tid] & 0xffffffffu);
        g_idx[i * KNB + tid] = j;
        if (out_idx) out_idx[i * KNB + tid] = (float)j;
    }
}

// ---------------- kernel 3: weight prep (fp16 fragment pack + folds) ----------------
__global__ __launch_bounds__(256) void k_prep(const float* __restrict__ wew,
                                              const float* __restrict__ pw,
                                              const float* __restrict__ lnw,
                                              const float* __restrict__ lnb,
                                              const float* __restrict__ pb) {
    int t = blockIdx.x * 256 + threadIdx.x;
    const int NB1 = NC1 * 1024;     // uint2 entries
    const int NB2 = NC2 * 1024;
    if (t < NB1) {
        int lane = t & 31, ks = (t >> 5) & 1, nt = (t >> 6) & 15, c = t >> 10;
        int g = lane >> 2, tt = lane & 3;
        int n = nt * 8 + g;
        int k = c * 32 + ks * 16 + 2 * tt;
        const float* src = wew + n * DFEAT;
        ((uint2*)g_B1)[t] = make_uint2(
            h2pack(make_float2(src[k],     src[k + 1])),
            h2pack(make_float2(src[k + 8], src[k + 9])));
    } else if (t < NB1 + NB2) {
        int t2 = t - NB1;
        int lane = t2 & 31, ks = (t2 >> 5) & 1, nt = (t2 >> 6) & 15, c = t2 >> 10;
        int g = lane >> 2, tt = lane & 3;
        int n = nt * 8 + g;
        int k = c * 32 + ks * 16 + 2 * tt;
        const float* src = pw + n * EDIM;
        ((uint2*)g_B2)[t2] = make_uint2(
            h2pack(make_float2(src[k] * lnw[k],         src[k + 1] * lnw[k + 1])),
            h2pack(make_float2(src[k + 8] * lnw[k + 8], src[k + 9] * lnw[k + 9])));
    } else if (t < NB1 + NB2 + EDIM) {
        int f = t - NB1 - NB2;
        float s = pb[f];
        for (int k = 0; k < EDIM; k++) s += pw[f * EDIM + k] * lnb[k];
        g_pbfold[f] = s;
    }
}

// ---------------- kernel 4: fused fp16 GEMMs, 64-edge tiles ----------------
// smem (bytes):
//   GEMM1 phase: A stage 2 x 5120 @0 | spd @10240 (6656) | swp @16896 (2240)
//   LN->GEMM2:   A2 fp16 64x136 @0 (17408)  [stage/spd/swp dead]
//   sRed @17536 (2048)
//   sB   @19712: 2 x 8192  (GEMM1 only; dead before epilogue stash)
//   epilogue: stash 64x132 f @0 (33792)
#define OFF_SPD  10240
#define OFF_SWP  16896
#define OFF_RED  17536
#define OFF_B    19712
#define SM_TOT   36864

__global__ void __launch_bounds__(256, 4) k_fused(
    const int* __restrict__ ri, const int* __restrict__ ci,
    const float* __restrict__ wpw, const float* __restrict__ wpb,
    float* __restrict__ out)
{
    extern __shared__ char smb[];
    float* spd = (float*)(smb + OFF_SPD);
    float* swp = (float*)(smb + OFF_SWP);
    float2* sRed = (float2*)(smb + OFF_RED);

    int tid = threadIdx.x, lane = tid & 31, warp = tid >> 5;
    int g = lane >> 2, tt = lane & 3;
    int mh = warp & 1, nh = warp >> 1;          // 2 x 4 warp grid
    int ldrow = (lane & 7) + ((lane >> 3) & 1) * 8;
    int ldcol = ((lane >> 4) & 1) * 16;
    int e0 = blockIdx.x * TILE;

    // ---- prelude ----
    int er = tid >> 2, q = tid & 3;
    int eg = e0 + er;
    int ii = eg / KNB;
    int jj = g_idx[eg];
    for (int p = tid; p < 560; p += 256)
        swp[p] = (p < 544) ? wpw[p] : wpb[p - 544];
    for (int p = tid; p < TILE * 25; p += 256) {
        int e = p / 25, pr = p - e * 25;
        int a = pr / 5, b2 = pr - a * 5;
        int ie = (e0 + e) / KNB;
        int je = g_idx[e0 + e];
        const float* bi = g_bb + ie * 15 + a * 3;
        const float* bj = g_bb + je * 15 + b2 * 3;
        float dx = bi[0] - bj[0], dy = bi[1] - bj[1], dz = bi[2] - bj[2];
        spd[e * 26 + pr] = __fsqrt_rn(dx*dx + dy*dy + dz*dz + 1e-6f);
    }
    int enc;
    {
        int ro = ri[ii] - ri[jj];
        enc = (ci[ii] == ci[jj]) ? min(max(ro + 16, 0), 32) : 33;
    }
    __syncthreads();   // publish spd/swp before any fillA reads

    auto fillA = [&](int c, int b) {
        float v[8];
        if (c == 0 && q < 2) {
            #pragma unroll
            for (int j = 0; j < 8; j++) {
                int f = q * 8 + j;
                v[j] = swp[f * 34 + enc] + swp[544 + f];
            }
        } else {
            int pdIdx = 2 * c - 1 + (q >> 1);
            float pd = spd[er * 26 + pdIdx];
            int binBase = (q & 1) * 8;
            #pragma unroll
            for (int j = 0; j < 8; j++) {
                float t = (pd - (2.0f + 1.3333334f * (float)(binBase + j))) * 0.8f;
                v[j] = fexp(-t * t);
            }
        }
        uint h[4];
        #pragma unroll
        for (int k = 0; k < 4; k++)
            h[k] = h2pack(make_float2(v[2*k], v[2*k+1]));
        *(uint4*)(smb + b * 5120 + er * 80 + q * 16) = make_uint4(h[0], h[1], h[2], h[3]);
    };
    auto stageB1 = [&](int c, int b) {
        const uint4* src = (const uint4*)(g_B1 + c * 2048);
        uint d = smaddr(smb + OFF_B) + b * 8192;
        CP16(d + tid * 16,        src + tid);
        CP16(d + 4096 + tid * 16, src + 256 + tid);
    };

    float acc[2][4][4];
    #pragma unroll
    for (int mt = 0; mt < 2; mt++)
        #pragma unroll
        for (int nt = 0; nt < 4; nt++)
            #pragma unroll
            for (int z = 0; z < 4; z++) acc[mt][nt][z] = 0.0f;

    // ================= GEMM1: one barrier per chunk (round-10 protocol) =======
    fillA(0, 0);
    stageB1(0, 0); CP_COMMIT();
    for (int c = 0; c < NC1; c++) {
        int b = c & 1;
        CP_WAIT(0);
        __syncthreads();   // publishes buf b; prior readers of b^1 passed here
        if (c + 1 < NC1) { stageB1(c + 1, b ^ 1); CP_COMMIT(); }

        #pragma unroll
        for (int ks = 0; ks < 2; ks++) {
            uint fa[2][4];
            #pragma unroll
            for (int mt = 0; mt < 2; mt++) {
                uint ad = smaddr(smb) + b * 5120
                        + (mh * 32 + mt * 16 + ldrow) * 80 + ks * 32 + ldcol;
                LDMX4(fa[mt], ad);
            }
            const uint2* bp = (const uint2*)(smb + OFF_B + b * 8192);
            #pragma unroll
            for (int nt = 0; nt < 4; nt++) {
                uint2 bv = bp[((nh * 4 + nt) * 2 + ks) * 32 + lane];
                #pragma unroll
                for (int mt = 0; mt < 2; mt++)
                    mma16h(acc[mt][nt], fa[mt], bv.x, bv.y);
            }
        }
        if (c + 1 < NC1) fillA(c + 1, b ^ 1);
    }

    // ================= LayerNorm -> fp16 A2 =================
    {
        float s[2][2], qq[2][2];
        #pragma unroll
        for (int mt = 0; mt < 2; mt++) {
            s[mt][0] = s[mt][1] = qq[mt][0] = qq[mt][1] = 0.f;
            #pragma unroll
            for (int nt = 0; nt < 4; nt++) {
                s[mt][0]  += acc[mt][nt][0] + acc[mt][nt][1];
                qq[mt][0] += acc[mt][nt][0]*acc[mt][nt][0] + acc[mt][nt][1]*acc[mt][nt][1];
                s[mt][1]  += acc[mt][nt][2] + acc[mt][nt][3];
                qq[mt][1] += acc[mt][nt][2]*acc[mt][nt][2] + acc[mt][nt][3]*acc[mt][nt][3];
            }
            #pragma unroll
            for (int off = 1; off <= 2; off <<= 1) {
                s[mt][0]  += __shfl_xor_sync(0xffffffffu, s[mt][0],  off);
                qq[mt][0] += __shfl_xor_sync(0xffffffffu, qq[mt][0], off);
                s[mt][1]  += __shfl_xor_sync(0xffffffffu, s[mt][1],  off);
                qq[mt][1] += __shfl_xor_sync(0xffffffffu, qq[mt][1], off);
            }
        }
        if (tt == 0) {
            #pragma unroll
            for (int mt = 0; mt < 2; mt++)
                #pragma unroll
                for (int rp = 0; rp < 2; rp++) {
                    int r = mh * 32 + mt * 16 + rp * 8 + g;
                    sRed[r * 4 + nh] = make_float2(s[mt][rp], qq[mt][rp]);
                }
        }
        __syncthreads();   // fences last GEMM1 stage reads before A2 overwrite
        float mean[2][2], rstd[2][2];
        #pragma unroll
        for (int mt = 0; mt < 2; mt++)
            #pragma unroll
            for (int rp = 0; rp < 2; rp++) {
                int r = mh * 32 + mt * 16 + rp * 8 + g;
                float S = 0.f, Q = 0.f;
                #pragma unroll
                for (int w = 0; w < 4; w++) {
                    float2 pq = sRed[r * 4 + w];
                    S += pq.x; Q += pq.y;
                }
                float m = S * (1.0f / 128.0f);
                mean[mt][rp] = m;
                rstd[mt][rp] = rsqrtf(Q * (1.0f / 128.0f) - m * m + 1e-5f);
            }
        #pragma unroll
        for (int mt = 0; mt < 2; mt++) {
            int r0 = mh * 32 + mt * 16 + g;
            #pragma unroll
            for (int nt = 0; nt < 4; nt++) {
                int C = nh * 32 + nt * 8 + 2 * tt;
                *(uint*)(smb + r0 * 272 + C * 2) = h2pack(make_float2(
                    (acc[mt][nt][0] - mean[mt][0]) * rstd[mt][0],
                    (acc[mt][nt][1] - mean[mt][0]) * rstd[mt][0]));
                *(uint*)(smb + (r0 + 8) * 272 + C * 2) = h2pack(make_float2(
                    (acc[mt][nt][2] - mean[mt][1]) * rstd[mt][1],
                    (acc[mt][nt][3] - mean[mt][1]) * rstd[mt][1]));
            }
        }
    }
    __syncthreads();

    // ================= GEMM2: A via ldmatrix, B via __ldg =================
    #pragma unroll
    for (int mt = 0; mt < 2; mt++)
        #pragma unroll
        for (int nt = 0; nt < 4; nt++)
            #pragma unroll
            for (int z = 0; z < 4; z++) acc[mt][nt][z] = 0.0f;

    #pragma unroll
    for (int c = 0; c < NC2; c++) {
        #pragma unroll
        for (int ks = 0; ks < 2; ks++) {
            uint fa[2][4];
            #pragma unroll
            for (int mt = 0; mt < 2; mt++) {
                uint ad = smaddr(smb)
                        + (mh * 32 + mt * 16 + ldrow) * 272 + c * 64 + ks * 32 + ldcol;
                LDMX4(fa[mt], ad);
            }
            #pragma unroll
            for (int nt = 0; nt < 4; nt++) {
                uint2 bv = __ldg((const uint2*)g_B2 +
                                 c * 1024 + ((nh * 4 + nt) * 2 + ks) * 32 + lane);
                #pragma unroll
                for (int mt = 0; mt < 2; mt++)
                    mma16h(acc[mt][nt], fa[mt], bv.x, bv.y);
            }
        }
    }

    // ================= epilogue =================
    __syncthreads();   // all A2 reads done before stash overwrite
    {
        float* stash = (float*)smb;
        #pragma unroll
        for (int mt = 0; mt < 2; mt++) {
            int r0 = mh * 32 + mt * 16 + g;
            #pragma unroll
            for (int nt = 0; nt < 4; nt++) {
                int C = nh * 32 + nt * 8 + 2 * tt;
                *(float2*)(stash + r0 * 132 + C)       = make_float2(acc[mt][nt][0], acc[mt][nt][1]);
                *(float2*)(stash + (r0 + 8) * 132 + C) = make_float2(acc[mt][nt][2], acc[mt][nt][3]);
            }
        }
    }
    __syncthreads();
    {
        const float* stash = (const float*)smb;
        int c4 = tid & 31;
        float4 bias = *(const float4*)(g_pbfold + c4 * 4);
        #pragma unroll
        for (int z = 0; z < 8; z++) {
            int idx = tid + 256 * z;
            int row = idx >> 5;
            float4 v = *(const float4*)(stash + row * 132 + c4 * 4);
            v.x += bias.x; v.y += bias.y; v.z += bias.z; v.w += bias.w;
            *(float4*)(out + (long long)(e0 + row) * EDIM + c4 * 4) = v;
        }
    }
}

// ---------------- launch ----------------
extern "C" void kernel_launch(void* const* d_in, const int* in_sizes, int n_in,
                              void* d_out, int out_size) {
    const float* coords = (const float*)d_in[0];
    const float* mask   = (const float*)d_in[1];
    const int*   ri     = (const int*)d_in[2];
    const int*   ci     = (const int*)d_in[3];
    const float* wpw    = (const float*)d_in[4];
    const float* wpb    = (const float*)d_in[5];
    const float* wew    = (const float*)d_in[6];
    const float* lnw    = (const float*)d_in[7];
    const float* lnb    = (const float*)d_in[8];
    const float* pw     = (const float*)d_in[9];
    const float* pb     = (const float*)d_in[10];
    float* out = (float*)d_out;

    long long main_elems = (long long)NEDGE * EDIM;
    float* out_idx = ((long long)out_size > main_elems) ? (out + main_elems) : nullptr;

    cudaFuncSetAttribute(k_fused, cudaFuncAttributeMaxDynamicSharedMemorySize, SM_TOT);

    k_backbone<<<(NRES + 255) / 256, 256>>>(coords);
    k_topk<<<NRES, 256>>>(mask, out_idx);
    k_prep<<<(NC1 * 1024 + NC2 * 1024 + EDIM + 255) / 256, 256>>>(wew, pw, lnw, lnb, pb);
    k_fused<<<NEDGE / TILE, 256, SM_TOT>>>(ri, ci, wpw, wpb, out);
}

// round 14
// speedup vs baseline: 1.6973x; 1.0829x over previous
#include <cuda_runtime.h>
#include <cstdint>

#define NRES 4096
#define KNB  48
#define EDIM 128
#define DFEAT 416
#define NEDGE (NRES*KNB)   // 196608
#define NC1 13
#define NC2 4
#define TILE 64            // edges per CTA

typedef unsigned int uint;
typedef unsigned long long ull;

// ---------------- device-global scratch ----------------
__device__ float g_bb[NRES * 15];
__device__ float g_ca[NRES * 3];
__device__ int   g_idx[NEDGE];
// fp16 weights pre-packed in m16n8k16 B-fragment layout (uint2 per lane entry).
__device__ __align__(16) uint g_B1[NC1 * 2048];
__device__ __align__(16) uint g_B2[NC2 * 2048];
__device__ float g_pbfold[EDIM];

// ---------------- helpers ----------------
__device__ __forceinline__ uint32_t smaddr(const void* p) {
    return (uint32_t)__cvta_generic_to_shared(p);
}
#define CP16(dst, src) \
    asm volatile("cp.async.cg.shared.global [%0], [%1], 16;" :: "r"(dst), "l"(src))
#define CP_COMMIT() asm volatile("cp.async.commit_group;" ::: "memory")
#define CP_WAIT(n)  asm volatile("cp.async.wait_group %0;" :: "n"(n) : "memory")

#define LDMX4(r, addr) \
    asm volatile("ldmatrix.sync.aligned.m8n8.x4.shared.b16 {%0,%1,%2,%3}, [%4];" \
        : "=r"((r)[0]), "=r"((r)[1]), "=r"((r)[2]), "=r"((r)[3]) : "r"(addr))

// pack float2 -> fp16x2 (v.x in low half)
__device__ __forceinline__ uint h2pack(float2 v) {
    uint h;
    asm("cvt.rn.f16x2.f32 %0, %1, %2;" : "=r"(h) : "f"(v.y), "f"(v.x));
    return h;
}

__device__ __forceinline__ void mma16h(float* d, const uint* a, uint b0, uint b1) {
    asm volatile(
        "mma.sync.aligned.m16n8k16.row.col.f32.f16.f16.f32 "
        "{%0,%1,%2,%3}, {%4,%5,%6,%7}, {%8,%9}, {%0,%1,%2,%3};"
        : "+f"(d[0]), "+f"(d[1]), "+f"(d[2]), "+f"(d[3])
        : "r"(a[0]), "r"(a[1]), "r"(a[2]), "r"(a[3]), "r"(b0), "r"(b1));
}

// exp(x), x<=0, pure FMA pipe. Degree-4 (rel err ~4e-5, << fp16 rounding).
__device__ __forceinline__ float fexp(float x) {
    x = fmaxf(x, -87.0f);
    float y  = x * 1.4426950408889634f;
    float z  = y + 12582912.0f;
    float nf = z - 12582912.0f;
    float g  = (y - nf) * 0.6931471805599453f;
    float p  = fmaf(g, 1.0f/24.0f, 1.0f/6.0f);
    p = fmaf(g, p, 0.5f);
    p = fmaf(g, p, 1.0f);
    p = fmaf(g, p, 1.0f);
    int n = __float_as_int(z) - 0x4B400000;
    return __int_as_float((n + 127) << 23) * p;
}

// ---------------- kernel 1: backbone + weight prep (merged) ----------------
// blocks [0,16): backbone; blocks [16, 16+69): prep
__global__ __launch_bounds__(256) void k_init(
    const float* __restrict__ coords,
    const float* __restrict__ wew, const float* __restrict__ pw,
    const float* __restrict__ lnw, const float* __restrict__ lnb,
    const float* __restrict__ pb)
{
    if (blockIdx.x < 16) {
        int i = blockIdx.x * 256 + threadIdx.x;
        if (i >= NRES) return;
        const float* p = coords + i * 12;
        float n0=p[0],n1=p[1],n2=p[2];
        float a0=p[3],a1=p[4],a2=p[5];
        float c0=p[6],c1=p[7],c2=p[8];
        float o0=p[9],o1=p[10],o2=p[11];
        float b0=a0-n0, b1=a1-n1, b2=a2-n2;
        float d0=c0-a0, d1=c1-a1, d2=c2-a2;
        float x0 = b1*d2 - b2*d1;
        float x1 = b2*d0 - b0*d2;
        float x2 = b0*d1 - b1*d0;
        float cb0 = -0.58273431f*x0 + 0.56802827f*b0 - 0.54067466f*d0 + a0;
        float cb1 = -0.58273431f*x1 + 0.56802827f*b1 - 0.54067466f*d1 + a1;
        float cb2 = -0.58273431f*x2 + 0.56802827f*b2 - 0.54067466f*d2 + a2;
        float* q = g_bb + i * 15;
        q[0]=n0; q[1]=n1; q[2]=n2;
        q[3]=a0; q[4]=a1; q[5]=a2;
        q[6]=c0; q[7]=c1; q[8]=c2;
        q[9]=o0; q[10]=o1; q[11]=o2;
        q[12]=cb0; q[13]=cb1; q[14]=cb2;
        g_ca[i] = a0; g_ca[NRES + i] = a1; g_ca[2*NRES + i] = a2;
        return;
    }
    int t = (blockIdx.x - 16) * 256 + threadIdx.x;
    const int NB1 = NC1 * 1024;     // uint2 entries
    const int NB2 = NC2 * 1024;
    if (t < NB1) {
        int lane = t & 31, ks = (t >> 5) & 1, nt = (t >> 6) & 15, c = t >> 10;
        int g = lane >> 2, tt = lane & 3;
        int n = nt * 8 + g;
        int k = c * 32 + ks * 16 + 2 * tt;
        const float* src = wew + n * DFEAT;
        ((uint2*)g_B1)[t] = make_uint2(
            h2pack(make_float2(src[k],     src[k + 1])),
            h2pack(make_float2(src[k + 8], src[k + 9])));
    } else if (t < NB1 + NB2) {
        int t2 = t - NB1;
        int lane = t2 & 31, ks = (t2 >> 5) & 1, nt = (t2 >> 6) & 15, c = t2 >> 10;
        int g = lane >> 2, tt = lane & 3;
        int n = nt * 8 + g;
        int k = c * 32 + ks * 16 + 2 * tt;
        const float* src = pw + n * EDIM;
        ((uint2*)g_B2)[t2] = make_uint2(
            h2pack(make_float2(src[k] * lnw[k],         src[k + 1] * lnw[k + 1])),
            h2pack(make_float2(src[k + 8] * lnw[k + 8], src[k + 9] * lnw[k + 9])));
    } else if (t < NB1 + NB2 + EDIM) {
        int f = t - NB1 - NB2;
        float s = pb[f];
        for (int k = 0; k < EDIM; k++) s += pw[f * EDIM + k] * lnb[k];
        g_pbfold[f] = s;
    }
}

// ---------------- kernel 2: exact 48-NN (rank-based selection, no sort) ----------------
__global__ __launch_bounds__(256) void k_topk(const float* __restrict__ mask,
                                              float* __restrict__ out_idx) {
    __shared__ float se[NRES];
    __shared__ uint  hist[1024];
    __shared__ ull   cand[2048];
    __shared__ uint  wsum[8];
    __shared__ int   s_thr, s_cnt;
    int i = blockIdx.x, tid = threadIdx.x;
    int lane = tid & 31, wid = tid >> 5;

    for (int b = tid; b < 1024; b += 256) hist[b] = 0;
    if (tid == 0) s_cnt = 0;
    float cax = g_ca[i], cay = g_ca[NRES + i], caz = g_ca[2*NRES + i];
    float mi = mask[i];
    __syncthreads();

    for (int j = tid; j < NRES; j += 256) {
        float dx = __fsub_rn(cax, g_ca[j]);
        float dy = __fsub_rn(cay, g_ca[NRES + j]);
        float dz = __fsub_rn(caz, g_ca[2*NRES + j]);
        float d2 = __fadd_rn(__fadd_rn(__fmul_rn(dx,dx), __fmul_rn(dy,dy)), __fmul_rn(dz,dz));
        float e  = __fadd_rn(d2, 1e-6f);
        if (__fmul_rn(mi, mask[j]) == 0.0f) e = __int_as_float(0x7f800000);
        se[j] = e;
        atomicAdd(&hist[__float_as_uint(e) >> 21], 1u);
    }
    __syncthreads();

    // parallel threshold: each thread owns 4 bins; prefix scan over 256 threads
    {
        int b0 = tid * 4;
        uint s4 = hist[b0] + hist[b0+1] + hist[b0+2] + hist[b0+3];
        uint v = s4;
        #pragma unroll
        for (int off = 1; off < 32; off <<= 1) {
            uint o = __shfl_up_sync(0xffffffffu, v, off);
            if (lane >= off) v += o;
        }
        if (lane == 31) wsum[wid] = v;
        __syncthreads();
        uint basec = 0;
        #pragma unroll
        for (int w = 0; w < 8; w++) if (w < wid) basec += wsum[w];
        uint incl = basec + v;
        uint excl = incl - s4;
        if (excl < KNB && KNB <= incl) {
            uint cum = excl; int b = b0;
            while (cum + hist[b] < KNB) { cum += hist[b]; b++; }
            s_thr = b;
        }
    }
    __syncthreads();
    uint B = (uint)s_thr;

    // candidate set: all j whose e-bin <= B (contains true top-48; bins monotone in dist)
    for (int j = tid; j < NRES; j += 256) {
        float e = se[j];
        if ((__float_as_uint(e) >> 21) <= B) {
            int p = atomicAdd(&s_cnt, 1);
            if (p < 2048) {
                float dist = __fsqrt_rn(e);   // exact dist for exact ordering
                cand[p] = ((ull)__float_as_uint(dist) << 32) | (uint)j;
            }
        }
    }
    __syncthreads();

    // rank-based selection: keys unique (idx in low bits) -> ranks are a permutation
    int C = min(s_cnt, 2048);
    for (int p = tid; p < C; p += 256) {
        ull my = cand[p];
        int rank = 0;
        for (int q = 0; q < C; q++) rank += (cand[q] < my) ? 1 : 0;
        if (rank < KNB) {
            int j = (int)(my & 0xffffffffu);
            g_idx[i * KNB + rank] = j;
            if (out_idx) out_idx[i * KNB + rank] = (float)j;
        }
    }
}

// ---------------- kernel 3: fused fp16 GEMMs, 64-edge tiles ----------------
// smem (bytes):
//   GEMM1 phase: A stage 2 x 5120 @0 | spd @10240 (6656) | swp @16896 (2240)
//   LN->GEMM2:   A2 fp16 64x136 @0 (17408)  [stage/spd/swp dead]
//   sRed @17536 (2048)
//   sB   @19712: 2 x 8192  (GEMM1 only)
//   epilogue: stash 64x132 f @0 (33792)
#define OFF_SPD  10240
#define OFF_SWP  16896
#define OFF_RED  17536
#define OFF_B    19712
#define SM_TOT   36864

__global__ void __launch_bounds__(256, 4) k_fused(
    const int* __restrict__ ri, const int* __restrict__ ci,
    const float* __restrict__ wpw, const float* __restrict__ wpb,
    float* __restrict__ out)
{
    extern __shared__ char smb[];
    float* spd = (float*)(smb + OFF_SPD);
    float* swp = (float*)(smb + OFF_SWP);
    float2* sRed = (float2*)(smb + OFF_RED);

    int tid = threadIdx.x, lane = tid & 31, warp = tid >> 5;
    int g = lane >> 2, tt = lane & 3;
    int mh = warp & 1, nh = warp >> 1;          // 2 x 4 warp grid
    int ldrow = (lane & 7) + ((lane >> 3) & 1) * 8;
    int ldcol = ((lane >> 4) & 1) * 16;
    int e0 = blockIdx.x * TILE;

    // ---- prelude ----
    int er = tid >> 2, q = tid & 3;
    int eg = e0 + er;
    int ii = eg / KNB;
    int jj = g_idx[eg];
    for (int p = tid; p < 560; p += 256)
        swp[p] = (p < 544) ? wpw[p] : wpb[p - 544];
    for (int p = tid; p < TILE * 25; p += 256) {
        int e = p / 25, pr = p - e * 25;
        int a = pr / 5, b2 = pr - a * 5;
        int ie = (e0 + e) / KNB;
        int je = g_idx[e0 + e];
        const float* bi = g_bb + ie * 15 + a * 3;
        const float* bj = g_bb + je * 15 + b2 * 3;
        float dx = bi[0] - bj[0], dy = bi[1] - bj[1], dz = bi[2] - bj[2];
        spd[e * 26 + pr] = __fsqrt_rn(dx*dx + dy*dy + dz*dz + 1e-6f);
    }
    int enc;
    {
        int ro = ri[ii] - ri[jj];
        enc = (ci[ii] == ci[jj]) ? min(max(ro + 16, 0), 32) : 33;
    }
    __syncthreads();   // publish spd/swp before any fillA reads

    auto fillA = [&](int c, int b) {
        float v[8];
        if (c == 0 && q < 2) {
            #pragma unroll
            for (int j = 0; j < 8; j++) {
                int f = q * 8 + j;
                v[j] = swp[f * 34 + enc] + swp[544 + f];
            }
        } else {
            int pdIdx = 2 * c - 1 + (q >> 1);
            float pd = spd[er * 26 + pdIdx];
            int binBase = (q & 1) * 8;
            #pragma unroll
            for (int j = 0; j < 8; j++) {
                float t = (pd - (2.0f + 1.3333334f * (float)(binBase + j))) * 0.8f;
                v[j] = fexp(-t * t);
            }
        }
        uint h[4];
        #pragma unroll
        for (int k = 0; k < 4; k++)
            h[k] = h2pack(make_float2(v[2*k], v[2*k+1]));
        *(uint4*)(smb + b * 5120 + er * 80 + q * 16) = make_uint4(h[0], h[1], h[2], h[3]);
    };
    auto stageB1 = [&](int c, int b) {
        const uint4* src = (const uint4*)(g_B1 + c * 2048);
        uint d = smaddr(smb + OFF_B) + b * 8192;
        CP16(d + tid * 16,        src + tid);
        CP16(d + 4096 + tid * 16, src + 256 + tid);
    };

    float acc[2][4][4];
    #pragma unroll
    for (int mt = 0; mt < 2; mt++)
        #pragma unroll
        for (int nt = 0; nt < 4; nt++)
            #pragma unroll
            for (int z = 0; z < 4; z++) acc[mt][nt][z] = 0.0f;

    // ================= GEMM1: one barrier per chunk =================
    fillA(0, 0);
    stageB1(0, 0); CP_COMMIT();
    for (int c = 0; c < NC1; c++) {
        int b = c & 1;
        CP_WAIT(0);
        __syncthreads();   // publishes buf b; prior readers of b^1 passed here
        if (c + 1 < NC1) { stageB1(c + 1, b ^ 1); CP_COMMIT(); }

        #pragma unroll
        for (int ks = 0; ks < 2; ks++) {
            uint fa[2][4];
            #pragma unroll
            for (int mt = 0; mt < 2; mt++) {
                uint ad = smaddr(smb) + b * 5120
                        + (mh * 32 + mt * 16 + ldrow) * 80 + ks * 32 + ldcol;
                LDMX4(fa[mt], ad);
            }
            const uint2* bp = (const uint2*)(smb + OFF_B + b * 8192);
            #pragma unroll
            for (int nt = 0; nt < 4; nt++) {
                uint2 bv = bp[((nh * 4 + nt) * 2 + ks) * 32 + lane];
                #pragma unroll
                for (int mt = 0; mt < 2; mt++)
                    mma16h(acc[mt][nt], fa[mt], bv.x, bv.y);
            }
        }
        if (c + 1 < NC1) fillA(c + 1, b ^ 1);
    }

    // ================= LayerNorm -> fp16 A2 =================
    {
        float s[2][2], qq[2][2];
        #pragma unroll
        for (int mt = 0; mt < 2; mt++) {
            s[mt][0] = s[mt][1] = qq[mt][0] = qq[mt][1] = 0.f;
            #pragma unroll
            for (int nt = 0; nt < 4; nt++) {
                s[mt][0]  += acc[mt][nt][0] + acc[mt][nt][1];
                qq[mt][0] += acc[mt][nt][0]*acc[mt][nt][0] + acc[mt][nt][1]*acc[mt][nt][1];
                s[mt][1]  += acc[mt][nt][2] + acc[mt][nt][3];
                qq[mt][1] += acc[mt][nt][2]*acc[mt][nt][2] + acc[mt][nt][3]*acc[mt][nt][3];
            }
            #pragma unroll
            for (int off = 1; off <= 2; off <<= 1) {
                s[mt][0]  += __shfl_xor_sync(0xffffffffu, s[mt][0],  off);
                qq[mt][0] += __shfl_xor_sync(0xffffffffu, qq[mt][0], off);
                s[mt][1]  += __shfl_xor_sync(0xffffffffu, s[mt][1],  off);
                qq[mt][1] += __shfl_xor_sync(0xffffffffu, qq[mt][1], off);
            }
        }
        if (tt == 0) {
            #pragma unroll
            for (int mt = 0; mt < 2; mt++)
                #pragma unroll
                for (int rp = 0; rp < 2; rp++) {
                    int r = mh * 32 + mt * 16 + rp * 8 + g;
                    sRed[r * 4 + nh] = make_float2(s[mt][rp], qq[mt][rp]);
                }
        }
        __syncthreads();   // fences last GEMM1 stage reads before A2 overwrite
        float mean[2][2], rstd[2][2];
        #pragma unroll
        for (int mt = 0; mt < 2; mt++)
            #pragma unroll
            for (int rp = 0; rp < 2; rp++) {
                int r = mh * 32 + mt * 16 + rp * 8 + g;
                float S = 0.f, Q = 0.f;
                #pragma unroll
                for (int w = 0; w < 4; w++) {
                    float2 pq = sRed[r * 4 + w];
                    S += pq.x; Q += pq.y;
                }
                float m = S * (1.0f / 128.0f);
                mean[mt][rp] = m;
                rstd[mt][rp] = rsqrtf(Q * (1.0f / 128.0f) - m * m + 1e-5f);
            }
        #pragma unroll
        for (int mt = 0; mt < 2; mt++) {
            int r0 = mh * 32 + mt * 16 + g;
            #pragma unroll
            for (int nt = 0; nt < 4; nt++) {
                int C = nh * 32 + nt * 8 + 2 * tt;
                *(uint*)(smb + r0 * 272 + C * 2) = h2pack(make_float2(
                    (acc[mt][nt][0] - mean[mt][0]) * rstd[mt][0],
                    (acc[mt][nt][1] - mean[mt][0]) * rstd[mt][0]));
                *(uint*)(smb + (r0 + 8) * 272 + C * 2) = h2pack(make_float2(
                    (acc[mt][nt][2] - mean[mt][1]) * rstd[mt][1],
                    (acc[mt][nt][3] - mean[mt][1]) * rstd[mt][1]));
            }
        }
    }
    __syncthreads();

    // ================= GEMM2: A via ldmatrix, B via __ldg =================
    #pragma unroll
    for (int mt = 0; mt < 2; mt++)
        #pragma unroll
        for (int nt = 0; nt < 4; nt++)
            #pragma unroll
            for (int z = 0; z < 4; z++) acc[mt][nt][z] = 0.0f;

    #pragma unroll
    for (int c = 0; c < NC2; c++) {
        #pragma unroll
        for (int ks = 0; ks < 2; ks++) {
            uint fa[2][4];
            #pragma unroll
            for (int mt = 0; mt < 2; mt++) {
                uint ad = smaddr(smb)
                        + (mh * 32 + mt * 16 + ldrow) * 272 + c * 64 + ks * 32 + ldcol;
                LDMX4(fa[mt], ad);
            }
            #pragma unroll
            for (int nt = 0; nt < 4; nt++) {
                uint2 bv = __ldg((const uint2*)g_B2 +
                                 c * 1024 + ((nh * 4 + nt) * 2 + ks) * 32 + lane);
                #pragma unroll
                for (int mt = 0; mt < 2; mt++)
                    mma16h(acc[mt][nt], fa[mt], bv.x, bv.y);
            }
        }
    }

    // ================= epilogue =================
    __syncthreads();   // all A2 reads done before stash overwrite
    {
        float* stash = (float*)smb;
        #pragma unroll
        for (int mt = 0; mt < 2; mt++) {
            int r0 = mh * 32 + mt * 16 + g;
            #pragma unroll
            for (int nt = 0; nt < 4; nt++) {
                int C = nh * 32 + nt * 8 + 2 * tt;
                *(float2*)(stash + r0 * 132 + C)       = make_float2(acc[mt][nt][0], acc[mt][nt][1]);
                *(float2*)(stash + (r0 + 8) * 132 + C) = make_float2(acc[mt][nt][2], acc[mt][nt][3]);
            }
        }
    }
    __syncthreads();
    {
        const float* stash = (const float*)smb;
        int c4 = tid & 31;
        float4 bias = *(const float4*)(g_pbfold + c4 * 4);
        #pragma unroll
        for (int z = 0; z < 8; z++) {
            int idx = tid + 256 * z;
            int row = idx >> 5;
            float4 v = *(const float4*)(stash + row * 132 + c4 * 4);
            v.x += bias.x; v.y += bias.y; v.z += bias.z; v.w += bias.w;
            *(float4*)(out + (long long)(e0 + row) * EDIM + c4 * 4) = v;
        }
    }
}

// ---------------- launch ----------------
extern "C" void kernel_launch(void* const* d_in, const int* in_sizes, int n_in,
                              void* d_out, int out_size) {
    const float* coords = (const float*)d_in[0];
    const float* mask   = (const float*)d_in[1];
    const int*   ri     = (const int*)d_in[2];
    const int*   ci     = (const int*)d_in[3];
    const float* wpw    = (const float*)d_in[4];
    const float* wpb    = (const float*)d_in[5];
    const float* wew    = (const float*)d_in[6];
    const float* lnw    = (const float*)d_in[7];
    const float* lnb    = (const float*)d_in[8];
    const float* pw     = (const float*)d_in[9];
    const float* pb     = (const float*)d_in[10];
    float* out = (float*)d_out;

    long long main_elems = (long long)NEDGE * EDIM;
    float* out_idx = ((long long)out_size > main_elems) ? (out + main_elems) : nullptr;

    cudaFuncSetAttribute(k_fused, cudaFuncAttributeMaxDynamicSharedMemorySize, SM_TOT);

    // k_init: 16 backbone blocks + ceil(((13+4)*1024 + 128)/256)=69 prep blocks
    k_init<<<16 + 69, 256>>>(coords, wew, pw, lnw, lnb, pb);
    k_topk<<<NRES, 256>>>(mask, out_idx);
    k_fused<<<NEDGE / TILE, 256, SM_TOT>>>(ri, ci, wpw, wpb, out);
}

// round 15
// speedup vs baseline: 1.8131x; 1.0682x over previous
#include <cuda_runtime.h>
#include <cstdint>

#define NRES 4096
#define KNB  48
#define EDIM 128
#define DFEAT 416
#define NEDGE (NRES*KNB)   // 196608
#define NC1 13
#define NC2 4
#define TILE 64            // edges per CTA

typedef unsigned int uint;
typedef unsigned long long ull;

// ---------------- device-global scratch ----------------
__device__ float g_bb[NRES * 15];
__device__ float g_ca[NRES * 3];
__device__ int   g_idx[NEDGE];
// fp16 weights pre-packed in m16n8k16 B-fragment layout (uint2 per lane entry).
__device__ __align__(16) uint g_B1[NC1 * 2048];
__device__ __align__(16) uint g_B2[NC2 * 2048];
__device__ float g_pbfold[EDIM];

// ---------------- helpers ----------------
__device__ __forceinline__ uint32_t smaddr(const void* p) {
    return (uint32_t)__cvta_generic_to_shared(p);
}
#define CP16(dst, src) \
    asm volatile("cp.async.cg.shared.global [%0], [%1], 16;" :: "r"(dst), "l"(src))
#define CP_COMMIT() asm volatile("cp.async.commit_group;" ::: "memory")
#define CP_WAIT(n)  asm volatile("cp.async.wait_group %0;" :: "n"(n) : "memory")

#define LDMX4(r, addr) \
    asm volatile("ldmatrix.sync.aligned.m8n8.x4.shared.b16 {%0,%1,%2,%3}, [%4];" \
        : "=r"((r)[0]), "=r"((r)[1]), "=r"((r)[2]), "=r"((r)[3]) : "r"(addr))

// pack float2 -> fp16x2 (v.x in low half)
__device__ __forceinline__ uint h2pack(float2 v) {
    uint h;
    asm("cvt.rn.f16x2.f32 %0, %1, %2;" : "=r"(h) : "f"(v.y), "f"(v.x));
    return h;
}

__device__ __forceinline__ void mma16h(float* d, const uint* a, uint b0, uint b1) {
    asm volatile(
        "mma.sync.aligned.m16n8k16.row.col.f32.f16.f16.f32 "
        "{%0,%1,%2,%3}, {%4,%5,%6,%7}, {%8,%9}, {%0,%1,%2,%3};"
        : "+f"(d[0]), "+f"(d[1]), "+f"(d[2]), "+f"(d[3])
        : "r"(a[0]), "r"(a[1]), "r"(a[2]), "r"(a[3]), "r"(b0), "r"(b1));
}

// exp(x), x<=0, pure FMA pipe. Degree-4 (rel err ~4e-5, << fp16 rounding).
__device__ __forceinline__ float fexp(float x) {
    x = fmaxf(x, -87.0f);
    float y  = x * 1.4426950408889634f;
    float z  = y + 12582912.0f;
    float nf = z - 12582912.0f;
    float g  = (y - nf) * 0.6931471805599453f;
    float p  = fmaf(g, 1.0f/24.0f, 1.0f/6.0f);
    p = fmaf(g, p, 0.5f);
    p = fmaf(g, p, 1.0f);
    p = fmaf(g, p, 1.0f);
    int n = __float_as_int(z) - 0x4B400000;
    return __int_as_float((n + 127) << 23) * p;
}

// ---------------- kernel 1: backbone + weight prep + pbfold (merged) -------------
// blocks [0,16): backbone; [16,84): fragment prep; [84,100): pbfold (warp-per-f)
__global__ __launch_bounds__(256) void k_init(
    const float* __restrict__ coords,
    const float* __restrict__ wew, const float* __restrict__ pw,
    const float* __restrict__ lnw, const float* __restrict__ lnb,
    const float* __restrict__ pb)
{
    if (blockIdx.x < 16) {
        int i = blockIdx.x * 256 + threadIdx.x;
        if (i >= NRES) return;
        const float* p = coords + i * 12;
        float n0=p[0],n1=p[1],n2=p[2];
        float a0=p[3],a1=p[4],a2=p[5];
        float c0=p[6],c1=p[7],c2=p[8];
        float o0=p[9],o1=p[10],o2=p[11];
        float b0=a0-n0, b1=a1-n1, b2=a2-n2;
        float d0=c0-a0, d1=c1-a1, d2=c2-a2;
        float x0 = b1*d2 - b2*d1;
        float x1 = b2*d0 - b0*d2;
        float x2 = b0*d1 - b1*d0;
        float cb0 = -0.58273431f*x0 + 0.56802827f*b0 - 0.54067466f*d0 + a0;
        float cb1 = -0.58273431f*x1 + 0.56802827f*b1 - 0.54067466f*d1 + a1;
        float cb2 = -0.58273431f*x2 + 0.56802827f*b2 - 0.54067466f*d2 + a2;
        float* q = g_bb + i * 15;
        q[0]=n0; q[1]=n1; q[2]=n2;
        q[3]=a0; q[4]=a1; q[5]=a2;
        q[6]=c0; q[7]=c1; q[8]=c2;
        q[9]=o0; q[10]=o1; q[11]=o2;
        q[12]=cb0; q[13]=cb1; q[14]=cb2;
        g_ca[i] = a0; g_ca[NRES + i] = a1; g_ca[2*NRES + i] = a2;
        return;
    }
    if (blockIdx.x < 84) {
        int t = (blockIdx.x - 16) * 256 + threadIdx.x;
        const int NB1 = NC1 * 1024;     // uint2 entries
        const int NB2 = NC2 * 1024;
        if (t < NB1) {
            int lane = t & 31, ks = (t >> 5) & 1, nt = (t >> 6) & 15, c = t >> 10;
            int g = lane >> 2, tt = lane & 3;
            int n = nt * 8 + g;
            int k = c * 32 + ks * 16 + 2 * tt;
            const float* src = wew + n * DFEAT;
            ((uint2*)g_B1)[t] = make_uint2(
                h2pack(make_float2(src[k],     src[k + 1])),
                h2pack(make_float2(src[k + 8], src[k + 9])));
        } else if (t < NB1 + NB2) {
            int t2 = t - NB1;
            int lane = t2 & 31, ks = (t2 >> 5) & 1, nt = (t2 >> 6) & 15, c = t2 >> 10;
            int g = lane >> 2, tt = lane & 3;
            int n = nt * 8 + g;
            int k = c * 32 + ks * 16 + 2 * tt;
            const float* src = pw + n * EDIM;
            ((uint2*)g_B2)[t2] = make_uint2(
                h2pack(make_float2(src[k] * lnw[k],         src[k + 1] * lnw[k + 1])),
                h2pack(make_float2(src[k + 8] * lnw[k + 8], src[k + 9] * lnw[k + 9])));
        }
        return;
    }
    // pbfold: warp-per-output, coalesced float4 loads, shfl reduce
    {
        int wid = threadIdx.x >> 5, lane = threadIdx.x & 31;
        int f = (blockIdx.x - 84) * 8 + wid;
        float4 w4 = *((const float4*)(pw + f * EDIM) + lane);
        float4 b4 = *((const float4*)lnb + lane);
        float s = w4.x * b4.x + w4.y * b4.y + w4.z * b4.z + w4.w * b4.w;
        #pragma unroll
        for (int off = 16; off; off >>= 1)
            s += __shfl_down_sync(0xffffffffu, s, off);
        if (lane == 0) g_pbfold[f] = pb[f] + s;
    }
}

// ---------------- kernel 2: exact 48-NN, 2 rows per block, e in registers ----------------
__global__ __launch_bounds__(256) void k_topk(const float* __restrict__ mask,
                                              float* __restrict__ out_idx) {
    __shared__ uint hist[2][1024];     // 8 KB
    __shared__ ull  cand[2][2048];     // 32 KB
    __shared__ uint wsum[8];
    __shared__ int  s_thr[2], s_cnt[2];
    int i0 = blockIdx.x * 2, i1 = i0 + 1;
    int tid = threadIdx.x, lane = tid & 31, wid = tid >> 5;

    for (int b = tid; b < 2048; b += 256) ((uint*)hist)[b] = 0;
    if (tid == 0) { s_cnt[0] = 0; s_cnt[1] = 0; }
    float ax0 = g_ca[i0], ay0 = g_ca[NRES + i0], az0 = g_ca[2*NRES + i0];
    float ax1 = g_ca[i1], ay1 = g_ca[NRES + i1], az1 = g_ca[2*NRES + i1];
    float m0 = mask[i0], m1 = mask[i1];
    __syncthreads();

    float e0[16], e1[16];
    #pragma unroll
    for (int z = 0; z < 16; z++) {
        int j = tid + 256 * z;
        float cx = g_ca[j], cy = g_ca[NRES + j], cz = g_ca[2*NRES + j];
        float mj = mask[j];
        float dx = __fsub_rn(ax0, cx), dy = __fsub_rn(ay0, cy), dz = __fsub_rn(az0, cz);
        float d2 = __fadd_rn(__fadd_rn(__fmul_rn(dx,dx), __fmul_rn(dy,dy)), __fmul_rn(dz,dz));
        float e  = __fadd_rn(d2, 1e-6f);
        if (__fmul_rn(m0, mj) == 0.0f) e = __int_as_float(0x7f800000);
        e0[z] = e;
        atomicAdd(&hist[0][__float_as_uint(e) >> 21], 1u);
        dx = __fsub_rn(ax1, cx); dy = __fsub_rn(ay1, cy); dz = __fsub_rn(az1, cz);
        d2 = __fadd_rn(__fadd_rn(__fmul_rn(dx,dx), __fmul_rn(dy,dy)), __fmul_rn(dz,dz));
        e  = __fadd_rn(d2, 1e-6f);
        if (__fmul_rn(m1, mj) == 0.0f) e = __int_as_float(0x7f800000);
        e1[z] = e;
        atomicAdd(&hist[1][__float_as_uint(e) >> 21], 1u);
    }
    __syncthreads();

    // parallel threshold per row (sequential over the 2 rows; cheap)
    for (int r = 0; r < 2; r++) {
        int b0 = tid * 4;
        uint s4 = hist[r][b0] + hist[r][b0+1] + hist[r][b0+2] + hist[r][b0+3];
        uint v = s4;
        #pragma unroll
        for (int off = 1; off < 32; off <<= 1) {
            uint o = __shfl_up_sync(0xffffffffu, v, off);
            if (lane >= off) v += o;
        }
        if (lane == 31) wsum[wid] = v;
        __syncthreads();
        uint basec = 0;
        #pragma unroll
        for (int w = 0; w < 8; w++) if (w < wid) basec += wsum[w];
        uint incl = basec + v;
        uint excl = incl - s4;
        if (excl < KNB && KNB <= incl) {
            uint cum = excl; int b = b0;
            while (cum + hist[r][b] < KNB) { cum += hist[r][b]; b++; }
            s_thr[r] = b;
        }
        __syncthreads();
    }
    uint B0 = (uint)s_thr[0], B1 = (uint)s_thr[1];

    // candidate collection from registers (exact sqrt only for candidates)
    #pragma unroll
    for (int z = 0; z < 16; z++) {
        int j = tid + 256 * z;
        float e = e0[z];
        if ((__float_as_uint(e) >> 21) <= B0) {
            int p = atomicAdd(&s_cnt[0], 1);
            if (p < 2048)
                cand[0][p] = ((ull)__float_as_uint(__fsqrt_rn(e)) << 32) | (uint)j;
        }
        e = e1[z];
        if ((__float_as_uint(e) >> 21) <= B1) {
            int p = atomicAdd(&s_cnt[1], 1);
            if (p < 2048)
                cand[1][p] = ((ull)__float_as_uint(__fsqrt_rn(e)) << 32) | (uint)j;
        }
    }
    __syncthreads();

    // rank-based selection per row (keys unique -> ranks are a permutation)
    #pragma unroll
    for (int r = 0; r < 2; r++) {
        int C = min(s_cnt[r], 2048);
        int i = (r == 0) ? i0 : i1;
        for (int p = tid; p < C; p += 256) {
            ull my = cand[r][p];
            int rank = 0;
            for (int q = 0; q < C; q++) rank += (cand[r][q] < my) ? 1 : 0;
            if (rank < KNB) {
                int j = (int)(my & 0xffffffffu);
                g_idx[i * KNB + rank] = j;
                if (out_idx) out_idx[i * KNB + rank] = (float)j;
            }
        }
    }
}

// ---------------- kernel 3: fused fp16 GEMMs, 64-edge tiles ----------------
// smem (bytes):
//   GEMM1 phase: A stage 2 x 5120 @0 | spd @10240 (6656) | swp @16896 (2240)
//   LN->GEMM2:   A2 fp16 64x136 @0 (17408)  [stage/spd/swp dead]
//   sRed @17536 (2048)
//   sB   @19712: 2 x 8192  (GEMM1 only)
#define OFF_SPD  10240
#define OFF_SWP  16896
#define OFF_RED  17536
#define OFF_B    19712
#define SM_TOT   36864

__global__ void __launch_bounds__(256, 4) k_fused(
    const int* __restrict__ ri, const int* __restrict__ ci,
    const float* __restrict__ wpw, const float* __restrict__ wpb,
    float* __restrict__ out)
{
    extern __shared__ char smb[];
    float* spd = (float*)(smb + OFF_SPD);
    float* swp = (float*)(smb + OFF_SWP);
    float2* sRed = (float2*)(smb + OFF_RED);

    int tid = threadIdx.x, lane = tid & 31, warp = tid >> 5;
    int g = lane >> 2, tt = lane & 3;
    int mh = warp & 1, nh = warp >> 1;          // 2 x 4 warp grid
    int ldrow = (lane & 7) + ((lane >> 3) & 1) * 8;
    int ldcol = ((lane >> 4) & 1) * 16;
    int e0 = blockIdx.x * TILE;

    // ---- prelude ----
    int er = tid >> 2, q = tid & 3;
    int eg = e0 + er;
    int ii = eg / KNB;
    int jj = g_idx[eg];
    for (int p = tid; p < 560; p += 256)
        swp[p] = (p < 544) ? wpw[p] : wpb[p - 544];
    for (int p = tid; p < TILE * 25; p += 256) {
        int e = p / 25, pr = p - e * 25;
        int a = pr / 5, b2 = pr - a * 5;
        int ie = (e0 + e) / KNB;
        int je = g_idx[e0 + e];
        const float* bi = g_bb + ie * 15 + a * 3;
        const float* bj = g_bb + je * 15 + b2 * 3;
        float dx = bi[0] - bj[0], dy = bi[1] - bj[1], dz = bi[2] - bj[2];
        spd[e * 26 + pr] = __fsqrt_rn(dx*dx + dy*dy + dz*dz + 1e-6f);
    }
    int enc;
    {
        int ro = ri[ii] - ri[jj];
        enc = (ci[ii] == ci[jj]) ? min(max(ro + 16, 0), 32) : 33;
    }
    __syncthreads();   // publish spd/swp before any fillA reads

    auto fillA = [&](int c, int b) {
        float v[8];
        if (c == 0 && q < 2) {
            #pragma unroll
            for (int j = 0; j < 8; j++) {
                int f = q * 8 + j;
                v[j] = swp[f * 34 + enc] + swp[544 + f];
            }
        } else {
            int pdIdx = 2 * c - 1 + (q >> 1);
            float pd = spd[er * 26 + pdIdx];
            int binBase = (q & 1) * 8;
            #pragma unroll
            for (int j = 0; j < 8; j++) {
                float t = (pd - (2.0f + 1.3333334f * (float)(binBase + j))) * 0.8f;
                v[j] = fexp(-t * t);
            }
        }
        uint h[4];
        #pragma unroll
        for (int k = 0; k < 4; k++)
            h[k] = h2pack(make_float2(v[2*k], v[2*k+1]));
        *(uint4*)(smb + b * 5120 + er * 80 + q * 16) = make_uint4(h[0], h[1], h[2], h[3]);
    };
    auto stageB1 = [&](int c, int b) {
        const uint4* src = (const uint4*)(g_B1 + c * 2048);
        uint d = smaddr(smb + OFF_B) + b * 8192;
        CP16(d + tid * 16,        src + tid);
        CP16(d + 4096 + tid * 16, src + 256 + tid);
    };

    float acc[2][4][4];
    #pragma unroll
    for (int mt = 0; mt < 2; mt++)
        #pragma unroll
        for (int nt = 0; nt < 4; nt++)
            #pragma unroll
            for (int z = 0; z < 4; z++) acc[mt][nt][z] = 0.0f;

    // ================= GEMM1: one barrier per chunk =================
    fillA(0, 0);
    stageB1(0, 0); CP_COMMIT();
    for (int c = 0; c < NC1; c++) {
        int b = c & 1;
        CP_WAIT(0);
        __syncthreads();   // publishes buf b; prior readers of b^1 passed here
        if (c + 1 < NC1) { stageB1(c + 1, b ^ 1); CP_COMMIT(); }

        #pragma unroll
        for (int ks = 0; ks < 2; ks++) {
            uint fa[2][4];
            #pragma unroll
            for (int mt = 0; mt < 2; mt++) {
                uint ad = smaddr(smb) + b * 5120
                        + (mh * 32 + mt * 16 + ldrow) * 80 + ks * 32 + ldcol;
                LDMX4(fa[mt], ad);
            }
            const uint2* bp = (const uint2*)(smb + OFF_B + b * 8192);
            #pragma unroll
            for (int nt = 0; nt < 4; nt++) {
                uint2 bv = bp[((nh * 4 + nt) * 2 + ks) * 32 + lane];
                #pragma unroll
                for (int mt = 0; mt < 2; mt++)
                    mma16h(acc[mt][nt], fa[mt], bv.x, bv.y);
            }
        }
        if (c + 1 < NC1) fillA(c + 1, b ^ 1);
    }

    // ================= LayerNorm -> fp16 A2 =================
    {
        float s[2][2], qq[2][2];
        #pragma unroll
        for (int mt = 0; mt < 2; mt++) {
            s[mt][0] = s[mt][1] = qq[mt][0] = qq[mt][1] = 0.f;
            #pragma unroll
            for (int nt = 0; nt < 4; nt++) {
                s[mt][0]  += acc[mt][nt][0] + acc[mt][nt][1];
                qq[mt][0] += acc[mt][nt][0]*acc[mt][nt][0] + acc[mt][nt][1]*acc[mt][nt][1];
                s[mt][1]  += acc[mt][nt][2] + acc[mt][nt][3];
                qq[mt][1] += acc[mt][nt][2]*acc[mt][nt][2] + acc[mt][nt][3]*acc[mt][nt][3];
            }
            #pragma unroll
            for (int off = 1; off <= 2; off <<= 1) {
                s[mt][0]  += __shfl_xor_sync(0xffffffffu, s[mt][0],  off);
                qq[mt][0] += __shfl_xor_sync(0xffffffffu, qq[mt][0], off);
                s[mt][1]  += __shfl_xor_sync(0xffffffffu, s[mt][1],  off);
                qq[mt][1] += __shfl_xor_sync(0xffffffffu, qq[mt][1], off);
            }
        }
        if (tt == 0) {
            #pragma unroll
            for (int mt = 0; mt < 2; mt++)
                #pragma unroll
                for (int rp = 0; rp < 2; rp++) {
                    int r = mh * 32 + mt * 16 + rp * 8 + g;
                    sRed[r * 4 + nh] = make_float2(s[mt][rp], qq[mt][rp]);
                }
        }
        __syncthreads();   // fences last GEMM1 stage reads before A2 overwrite
        float mean[2][2], rstd[2][2];
        #pragma unroll
        for (int mt = 0; mt < 2; mt++)
            #pragma unroll
            for (int rp = 0; rp < 2; rp++) {
                int r = mh * 32 + mt * 16 + rp * 8 + g;
                float S = 0.f, Q = 0.f;
                #pragma unroll
                for (int w = 0; w < 4; w++) {
                    float2 pq = sRed[r * 4 + w];
                    S += pq.x; Q += pq.y;
                }
                float m = S * (1.0f / 128.0f);
                mean[mt][rp] = m;
                rstd[mt][rp] = rsqrtf(Q * (1.0f / 128.0f) - m * m + 1e-5f);
            }
        #pragma unroll
        for (int mt = 0; mt < 2; mt++) {
            int r0 = mh * 32 + mt * 16 + g;
            #pragma unroll
            for (int nt = 0; nt < 4; nt++) {
                int C = nh * 32 + nt * 8 + 2 * tt;
                *(uint*)(smb + r0 * 272 + C * 2) = h2pack(make_float2(
                    (acc[mt][nt][0] - mean[mt][0]) * rstd[mt][0],
                    (acc[mt][nt][1] - mean[mt][0]) * rstd[mt][0]));
                *(uint*)(smb + (r0 + 8) * 272 + C * 2) = h2pack(make_float2(
                    (acc[mt][nt][2] - mean[mt][1]) * rstd[mt][1],
                    (acc[mt][nt][3] - mean[mt][1]) * rstd[mt][1]));
            }
        }
    }
    __syncthreads();

    // ================= GEMM2: A via ldmatrix, B via __ldg =================
    #pragma unroll
    for (int mt = 0; mt < 2; mt++)
        #pragma unroll
        for (int nt = 0; nt < 4; nt++)
            #pragma unroll
            for (int z = 0; z < 4; z++) acc[mt][nt][z] = 0.0f;

    #pragma unroll
    for (int c = 0; c < NC2; c++) {
        #pragma unroll
        for (int ks = 0; ks < 2; ks++) {
            uint fa[2][4];
            #pragma unroll
            for (int mt = 0; mt < 2; mt++) {
                uint ad = smaddr(smb)
                        + (mh * 32 + mt * 16 + ldrow) * 272 + c * 64 + ks * 32 + ldcol;
                LDMX4(fa[mt], ad);
            }
            #pragma unroll
            for (int nt = 0; nt < 4; nt++) {
                uint2 bv = __ldg((const uint2*)g_B2 +
                                 c * 1024 + ((nh * 4 + nt) * 2 + ks) * 32 + lane);
                #pragma unroll
                for (int mt = 0; mt < 2; mt++)
                    mma16h(acc[mt][nt], fa[mt], bv.x, bv.y);
            }
        }
    }

    // ================= epilogue: direct fragment -> global stores =================
    // lane (g,tt) of warp (mh,nh): rows e0+mh*32+mt*16+{g, g+8}, cols nh*32+nt*8+2tt..+1
    #pragma unroll
    for (int nt = 0; nt < 4; nt++) {
        int C = nh * 32 + nt * 8 + 2 * tt;
        float2 bv = __ldg((const float2*)(g_pbfold + C));
        #pragma unroll
        for (int mt = 0; mt < 2; mt++) {
            int r0 = e0 + mh * 32 + mt * 16 + g;
            *(float2*)(out + (long long)r0 * EDIM + C) =
                make_float2(acc[mt][nt][0] + bv.x, acc[mt][nt][1] + bv.y);
            *(float2*)(out + (long long)(r0 + 8) * EDIM + C) =
                make_float2(acc[mt][nt][2] + bv.x, acc[mt][nt][3] + bv.y);
        }
    }
}

// ---------------- launch ----------------
extern "C" void kernel_launch(void* const* d_in, const int* in_sizes, int n_in,
                              void* d_out, int out_size) {
    const float* coords = (const float*)d_in[0];
    const float* mask   = (const float*)d_in[1];
    const int*   ri     = (const int*)d_in[2];
    const int*   ci     = (const int*)d_in[3];
    const float* wpw    = (const float*)d_in[4];
    const float* wpb    = (const float*)d_in[5];
    const float* wew    = (const float*)d_in[6];
    const float* lnw    = (const float*)d_in[7];
    const float* lnb    = (const float*)d_in[8];
    const float* pw     = (const float*)d_in[9];
    const float* pb     = (const float*)d_in[10];
    float* out = (float*)d_out;

    long long main_elems = (long long)NEDGE * EDIM;
    float* out_idx = ((long long)out_size > main_elems) ? (out + main_elems) : nullptr;

    cudaFuncSetAttribute(k_fused, cudaFuncAttributeMaxDynamicSharedMemorySize, SM_TOT);

    // k_init: 16 backbone + 68 prep + 16 pbfold = 100 blocks
    k_init<<<100, 256>>>(coords, wew, pw, lnw, lnb, pb);
    k_topk<<<NRES / 2, 256>>>(mask, out_idx);
    k_fused<<<NEDGE / TILE, 256, SM_TOT>>>(ri, ci, wpw, wpb, out);
}

// round 17
// speedup vs baseline: 1.8569x; 1.0242x over previous
#include <cuda_runtime.h>
#include <cstdint>

#define NRES 4096
#define KNB  48
#define EDIM 128
#define DFEAT 416
#define NEDGE (NRES*KNB)   // 196608
#define NC1 13
#define NC2 4
#define TILE 64            // edges per CTA

typedef unsigned int uint;
typedef unsigned long long ull;

// ---------------- device-global scratch ----------------
__device__ float g_bb[NRES * 15];
__device__ float g_ca[NRES * 3];
__device__ int   g_idx[NEDGE];
// fp16 weights pre-packed in m16n8k16 B-fragment layout (uint2 per lane entry).
__device__ __align__(16) uint g_B1[NC1 * 2048];
__device__ __align__(16) uint g_B2[NC2 * 2048];
__device__ float g_pbfold[EDIM];

// ---------------- helpers ----------------
__device__ __forceinline__ uint32_t smaddr(const void* p) {
    return (uint32_t)__cvta_generic_to_shared(p);
}
#define CP16(dst, src) \
    asm volatile("cp.async.cg.shared.global [%0], [%1], 16;" :: "r"(dst), "l"(src))
#define CP_COMMIT() asm volatile("cp.async.commit_group;" ::: "memory")
#define CP_WAIT(n)  asm volatile("cp.async.wait_group %0;" :: "n"(n) : "memory")

#define LDMX4(r, addr) \
    asm volatile("ldmatrix.sync.aligned.m8n8.x4.shared.b16 {%0,%1,%2,%3}, [%4];" \
        : "=r"((r)[0]), "=r"((r)[1]), "=r"((r)[2]), "=r"((r)[3]) : "r"(addr))

// pack float2 -> fp16x2 (v.x in low half)
__device__ __forceinline__ uint h2pack(float2 v) {
    uint h;
    asm("cvt.rn.f16x2.f32 %0, %1, %2;" : "=r"(h) : "f"(v.y), "f"(v.x));
    return h;
}

__device__ __forceinline__ void mma16h(float* d, const uint* a, uint b0, uint b1) {
    asm volatile(
        "mma.sync.aligned.m16n8k16.row.col.f32.f16.f16.f32 "
        "{%0,%1,%2,%3}, {%4,%5,%6,%7}, {%8,%9}, {%0,%1,%2,%3};"
        : "+f"(d[0]), "+f"(d[1]), "+f"(d[2]), "+f"(d[3])
        : "r"(a[0]), "r"(a[1]), "r"(a[2]), "r"(a[3]), "r"(b0), "r"(b1));
}

// exp(x), pure FMA pipe, degree-6 (rel err ~1e-8). Valid for x in [-87, ~10].
__device__ __forceinline__ float fexp(float x) {
    x = fmaxf(x, -87.0f);
    float y  = x * 1.4426950408889634f;
    float z  = y + 12582912.0f;
    float nf = z - 12582912.0f;
    float g  = (y - nf) * 0.6931471805599453f;
    float p  = fmaf(g, 1.0f/720.0f, 1.0f/120.0f);
    p = fmaf(g, p, 1.0f/24.0f);
    p = fmaf(g, p, 1.0f/6.0f);
    p = fmaf(g, p, 0.5f);
    p = fmaf(g, p, 1.0f);
    p = fmaf(g, p, 1.0f);
    int n = __float_as_int(z) - 0x4B400000;
    return __int_as_float((n + 127) << 23) * p;
}

// ---------------- kernel 1: backbone + weight prep + pbfold (merged) -------------
__global__ __launch_bounds__(256) void k_init(
    const float* __restrict__ coords,
    const float* __restrict__ wew, const float* __restrict__ pw,
    const float* __restrict__ lnw, const float* __restrict__ lnb,
    const float* __restrict__ pb)
{
    if (blockIdx.x < 16) {
        int i = blockIdx.x * 256 + threadIdx.x;
        if (i >= NRES) return;
        const float* p = coords + i * 12;
        float n0=p[0],n1=p[1],n2=p[2];
        float a0=p[3],a1=p[4],a2=p[5];
        float c0=p[6],c1=p[7],c2=p[8];
        float o0=p[9],o1=p[10],o2=p[11];
        float b0=a0-n0, b1=a1-n1, b2=a2-n2;
        float d0=c0-a0, d1=c1-a1, d2=c2-a2;
        float x0 = b1*d2 - b2*d1;
        float x1 = b2*d0 - b0*d2;
        float x2 = b0*d1 - b1*d0;
        float cb0 = -0.58273431f*x0 + 0.56802827f*b0 - 0.54067466f*d0 + a0;
        float cb1 = -0.58273431f*x1 + 0.56802827f*b1 - 0.54067466f*d1 + a1;
        float cb2 = -0.58273431f*x2 + 0.56802827f*b2 - 0.54067466f*d2 + a2;
        float* q = g_bb + i * 15;
        q[0]=n0; q[1]=n1; q[2]=n2;
        q[3]=a0; q[4]=a1; q[5]=a2;
        q[6]=c0; q[7]=c1; q[8]=c2;
        q[9]=o0; q[10]=o1; q[11]=o2;
        q[12]=cb0; q[13]=cb1; q[14]=cb2;
        g_ca[i] = a0; g_ca[NRES + i] = a1; g_ca[2*NRES + i] = a2;
        return;
    }
    if (blockIdx.x < 84) {
        int t = (blockIdx.x - 16) * 256 + threadIdx.x;
        const int NB1 = NC1 * 1024;     // uint2 entries
        const int NB2 = NC2 * 1024;
        if (t < NB1) {
            int lane = t & 31, ks = (t >> 5) & 1, nt = (t >> 6) & 15, c = t >> 10;
            int g = lane >> 2, tt = lane & 3;
            int n = nt * 8 + g;
            int k = c * 32 + ks * 16 + 2 * tt;
            const float* src = wew + n * DFEAT;
            ((uint2*)g_B1)[t] = make_uint2(
                h2pack(make_float2(src[k],     src[k + 1])),
                h2pack(make_float2(src[k + 8], src[k + 9])));
        } else if (t < NB1 + NB2) {
            int t2 = t - NB1;
            int lane = t2 & 31, ks = (t2 >> 5) & 1, nt = (t2 >> 6) & 15, c = t2 >> 10;
            int g = lane >> 2, tt = lane & 3;
            int n = nt * 8 + g;
            int k = c * 32 + ks * 16 + 2 * tt;
            const float* src = pw + n * EDIM;
            ((uint2*)g_B2)[t2] = make_uint2(
                h2pack(make_float2(src[k] * lnw[k],         src[k + 1] * lnw[k + 1])),
                h2pack(make_float2(src[k + 8] * lnw[k + 8], src[k + 9] * lnw[k + 9])));
        }
        return;
    }
    // pbfold: warp-per-output, coalesced float4 loads, shfl reduce
    {
        int wid = threadIdx.x >> 5, lane = threadIdx.x & 31;
        int f = (blockIdx.x - 84) * 8 + wid;
        float4 w4 = *((const float4*)(pw + f * EDIM) + lane);
        float4 b4 = *((const float4*)lnb + lane);
        float s = w4.x * b4.x + w4.y * b4.y + w4.z * b4.z + w4.w * b4.w;
        #pragma unroll
        for (int off = 16; off; off >>= 1)
            s += __shfl_down_sync(0xffffffffu, s, off);
        if (lane == 0) g_pbfold[f] = pb[f] + s;
    }
}

// ---------------- kernel 2: exact 48-NN, 4 rows per block (dynamic smem) ----------------
#define CCAP 1024
#define TOPK_SMEM (4*1024*4 + 4*CCAP*8)   // hist 16384 + cand 32768 = 49152
__global__ __launch_bounds__(256) void k_topk(const float* __restrict__ mask,
                                              float* __restrict__ out_idx) {
    extern __shared__ char tsm[];
    uint (*hist)[1024] = (uint (*)[1024])tsm;            // 4 x 1024 uints
    ull  (*cand)[CCAP] = (ull (*)[CCAP])(tsm + 16384);   // 4 x CCAP ulls
    __shared__ uint wsum[8];
    __shared__ int  s_thr[4], s_cnt[4];
    int i0 = blockIdx.x * 4;
    int tid = threadIdx.x, lane = tid & 31, wid = tid >> 5;

    for (int b = tid; b < 4096; b += 256) ((uint*)hist)[b] = 0;
    if (tid < 4) s_cnt[tid] = 0;
    float ax[4], ay[4], az[4], mr[4];
    #pragma unroll
    for (int r = 0; r < 4; r++) {
        ax[r] = g_ca[i0 + r]; ay[r] = g_ca[NRES + i0 + r]; az[r] = g_ca[2*NRES + i0 + r];
        mr[r] = mask[i0 + r];
    }
    __syncthreads();

    float ev[4][16];
    #pragma unroll
    for (int z = 0; z < 16; z++) {
        int j = tid + 256 * z;
        float cx = g_ca[j], cy = g_ca[NRES + j], cz = g_ca[2*NRES + j];
        float mj = mask[j];
        #pragma unroll
        for (int r = 0; r < 4; r++) {
            float dx = __fsub_rn(ax[r], cx), dy = __fsub_rn(ay[r], cy), dz = __fsub_rn(az[r], cz);
            float d2 = __fadd_rn(__fadd_rn(__fmul_rn(dx,dx), __fmul_rn(dy,dy)), __fmul_rn(dz,dz));
            float e  = __fadd_rn(d2, 1e-6f);
            if (__fmul_rn(mr[r], mj) == 0.0f) e = __int_as_float(0x7f800000);
            ev[r][z] = e;
            atomicAdd(&hist[r][__float_as_uint(e) >> 21], 1u);
        }
    }
    __syncthreads();

    // parallel threshold per row
    for (int r = 0; r < 4; r++) {
        int b0 = tid * 4;
        uint s4 = hist[r][b0] + hist[r][b0+1] + hist[r][b0+2] + hist[r][b0+3];
        uint v = s4;
        #pragma unroll
        for (int off = 1; off < 32; off <<= 1) {
            uint o = __shfl_up_sync(0xffffffffu, v, off);
            if (lane >= off) v += o;
        }
        if (lane == 31) wsum[wid] = v;
        __syncthreads();
        uint basec = 0;
        #pragma unroll
        for (int w = 0; w < 8; w++) if (w < wid) basec += wsum[w];
        uint incl = basec + v;
        uint excl = incl - s4;
        if (excl < KNB && KNB <= incl) {
            uint cum = excl; int b = b0;
            while (cum + hist[r][b] < KNB) { cum += hist[r][b]; b++; }
            s_thr[r] = b;
        }
        __syncthreads();   // guards wsum reuse + publishes s_thr
    }
    uint B[4];
    #pragma unroll
    for (int r = 0; r < 4; r++) B[r] = (uint)s_thr[r];

    // candidate collection from registers (sqrt only for candidates)
    #pragma unroll
    for (int z = 0; z < 16; z++) {
        int j = tid + 256 * z;
        #pragma unroll
        for (int r = 0; r < 4; r++) {
            float e = ev[r][z];
            if ((__float_as_uint(e) >> 21) <= B[r]) {
                int p = atomicAdd(&s_cnt[r], 1);
                if (p < CCAP)
                    cand[r][p] = ((ull)__float_as_uint(__fsqrt_rn(e)) << 32) | (uint)j;
            }
        }
    }
    __syncthreads();

    // rank-based selection per row (keys unique -> ranks are a permutation)
    for (int r = 0; r < 4; r++) {
        int C = min(s_cnt[r], CCAP);
        int i = i0 + r;
        for (int p = tid; p < C; p += 256) {
            ull my = cand[r][p];
            int rank = 0;
            for (int q = 0; q < C; q++) rank += (cand[r][q] < my) ? 1 : 0;
            if (rank < KNB) {
                int j = (int)(my & 0xffffffffu);
                g_idx[i * KNB + rank] = j;
                if (out_idx) out_idx[i * KNB + rank] = (float)j;
            }
        }
    }
}

// ---------------- kernel 3: fused fp16 GEMMs, 64-edge tiles ----------------
#define OFF_SPD  10240
#define OFF_SWP  16896
#define OFF_RED  17536
#define OFF_B    19712
#define SM_TOT   36864

__global__ void __launch_bounds__(256, 4) k_fused(
    const int* __restrict__ ri, const int* __restrict__ ci,
    const float* __restrict__ wpw, const float* __restrict__ wpb,
    float* __restrict__ out)
{
    extern __shared__ char smb[];
    float* spd = (float*)(smb + OFF_SPD);
    float* swp = (float*)(smb + OFF_SWP);
    float2* sRed = (float2*)(smb + OFF_RED);

    int tid = threadIdx.x, lane = tid & 31, warp = tid >> 5;
    int g = lane >> 2, tt = lane & 3;
    int mh = warp & 1, nh = warp >> 1;          // 2 x 4 warp grid
    int ldrow = (lane & 7) + ((lane >> 3) & 1) * 8;
    int ldcol = ((lane >> 4) & 1) * 16;
    int e0 = blockIdx.x * TILE;

    // ---- prelude ----
    int er = tid >> 2, q = tid & 3;
    int eg = e0 + er;
    int ii = eg / KNB;
    int jj = g_idx[eg];
    for (int p = tid; p < 560; p += 256)
        swp[p] = (p < 544) ? wpw[p] : wpb[p - 544];
    for (int p = tid; p < TILE * 25; p += 256) {
        int e = p / 25, pr = p - e * 25;
        int a = pr / 5, b2 = pr - a * 5;
        int ie = (e0 + e) / KNB;
        int je = g_idx[e0 + e];
        const float* bi = g_bb + ie * 15 + a * 3;
        const float* bj = g_bb + je * 15 + b2 * 3;
        float dx = bi[0] - bj[0], dy = bi[1] - bj[1], dz = bi[2] - bj[2];
        spd[e * 26 + pr] = __fsqrt_rn(dx*dx + dy*dy + dz*dz + 1e-6f);
    }
    int enc;
    {
        int ro = ri[ii] - ri[jj];
        enc = (ci[ii] == ci[jj]) ? min(max(ro + 16, 0), 32) : 33;
    }
    __syncthreads();   // publish spd/swp before any fillA reads

    auto fillA = [&](int c, int b) {
        float v[8];
        if (c == 0 && q < 2) {
            #pragma unroll
            for (int j = 0; j < 8; j++) {
                int f = q * 8 + j;
                v[j] = swp[f * 34 + enc] + swp[544 + f];
            }
        } else {
            // RBF via ratio recurrence: v_{j+1} = v_j * r, r *= rho (2 fexp + 14 mul)
            int pdIdx = 2 * c - 1 + (q >> 1);
            float pd = spd[er * 26 + pdIdx];
            int binBase = (q & 1) * 8;
            float mu0 = 2.0f + 1.3333334f * (float)binBase;
            const float c1   = 1.0666667f;     // 0.8 * 4/3
            const float c1sq = 1.1377778f;     // c1^2
            const float rho  = 0.10273992f;    // exp(-2*c1^2)
            if (pd < mu0 + 4.6666667f) {       // start at nearest end: j=0, chain up
                float t0 = (pd - mu0) * 0.8f;
                float vv = fexp(-t0 * t0);
                float r  = fexp(fmaf(2.0f * c1, t0, -c1sq));
                v[0] = vv;
                #pragma unroll
                for (int j = 1; j < 8; j++) { vv *= r; r *= rho; v[j] = vv; }
            } else {                           // start at j=7, chain down
                float t7 = (pd - (mu0 + 9.3333333f)) * 0.8f;
                float vv = fexp(-t7 * t7);
                float r  = fexp(fmaf(-2.0f * c1, t7, -c1sq));
                v[7] = vv;
                #pragma unroll
                for (int j = 6; j >= 0; j--) { vv *= r; r *= rho; v[j] = vv; }
            }
        }
        uint h[4];
        #pragma unroll
        for (int k = 0; k < 4; k++)
            h[k] = h2pack(make_float2(v[2*k], v[2*k+1]));
        *(uint4*)(smb + b * 5120 + er * 80 + q * 16) = make_uint4(h[0], h[1], h[2], h[3]);
    };
    auto stageB1 = [&](int c, int b) {
        const uint4* src = (const uint4*)(g_B1 + c * 2048);
        uint d = smaddr(smb + OFF_B) + b * 8192;
        CP16(d + tid * 16,        src + tid);
        CP16(d + 4096 + tid * 16, src + 256 + tid);
    };

    float acc[2][4][4];
    #pragma unroll
    for (int mt = 0; mt < 2; mt++)
        #pragma unroll
        for (int nt = 0; nt < 4; nt++)
            #pragma unroll
            for (int z = 0; z < 4; z++) acc[mt][nt][z] = 0.0f;

    // ================= GEMM1: one barrier per chunk =================
    fillA(0, 0);
    stageB1(0, 0); CP_COMMIT();
    for (int c = 0; c < NC1; c++) {
        int b = c & 1;
        CP_WAIT(0);
        __syncthreads();   // publishes buf b; prior readers of b^1 passed here
        if (c + 1 < NC1) { stageB1(c + 1, b ^ 1); CP_COMMIT(); }

        #pragma unroll
        for (int ks = 0; ks < 2; ks++) {
            uint fa[2][4];
            #pragma unroll
            for (int mt = 0; mt < 2; mt++) {
                uint ad = smaddr(smb) + b * 5120
                        + (mh * 32 + mt * 16 + ldrow) * 80 + ks * 32 + ldcol;
                LDMX4(fa[mt], ad);
            }
            const uint2* bp = (const uint2*)(smb + OFF_B + b * 8192);
            #pragma unroll
            for (int nt = 0; nt < 4; nt++) {
                uint2 bv = bp[((nh * 4 + nt) * 2 + ks) * 32 + lane];
                #pragma unroll
                for (int mt = 0; mt < 2; mt++)
                    mma16h(acc[mt][nt], fa[mt], bv.x, bv.y);
            }
        }
        if (c + 1 < NC1) fillA(c + 1, b ^ 1);
    }

    // ================= LayerNorm -> fp16 A2 =================
    {
        float s[2][2], qq[2][2];
        #pragma unroll
        for (int mt = 0; mt < 2; mt++) {
            s[mt][0] = s[mt][1] = qq[mt][0] = qq[mt][1] = 0.f;
            #pragma unroll
            for (int nt = 0; nt < 4; nt++) {
                s[mt][0]  += acc[mt][nt][0] + acc[mt][nt][1];
                qq[mt][0] += acc[mt][nt][0]*acc[mt][nt][0] + acc[mt][nt][1]*acc[mt][nt][1];
                s[mt][1]  += acc[mt][nt][2] + acc[mt][nt][3];
                qq[mt][1] += acc[mt][nt][2]*acc[mt][nt][2] + acc[mt][nt][3]*acc[mt][nt][3];
            }
            #pragma unroll
            for (int off = 1; off <= 2; off <<= 1) {
                s[mt][0]  += __shfl_xor_sync(0xffffffffu, s[mt][0],  off);
                qq[mt][0] += __shfl_xor_sync(0xffffffffu, qq[mt][0], off);
                s[mt][1]  += __shfl_xor_sync(0xffffffffu, s[mt][1],  off);
                qq[mt][1] += __shfl_xor_sync(0xffffffffu, qq[mt][1], off);
            }
        }
        if (tt == 0) {
            #pragma unroll
            for (int mt = 0; mt < 2; mt++)
                #pragma unroll
                for (int rp = 0; rp < 2; rp++) {
                    int r = mh * 32 + mt * 16 + rp * 8 + g;
                    sRed[r * 4 + nh] = make_float2(s[mt][rp], qq[mt][rp]);
                }
        }
        __syncthreads();   // fences last GEMM1 stage reads before A2 overwrite
        float mean[2][2], rstd[2][2];
        #pragma unroll
        for (int mt = 0; mt < 2; mt++)
            #pragma unroll
            for (int rp = 0; rp < 2; rp++) {
                int r = mh * 32 + mt * 16 + rp * 8 + g;
                float S = 0.f, Q = 0.f;
                #pragma unroll
                for (int w = 0; w < 4; w++) {
                    float2 pq = sRed[r * 4 + w];
                    S += pq.x; Q += pq.y;
                }
                float m = S * (1.0f / 128.0f);
                mean[mt][rp] = m;
                rstd[mt][rp] = rsqrtf(Q * (1.0f / 128.0f) - m * m + 1e-5f);
            }
        #pragma unroll
        for (int mt = 0; mt < 2; mt++) {
            int r0 = mh * 32 + mt * 16 + g;
            #pragma unroll
            for (int nt = 0; nt < 4; nt++) {
                int C = nh * 32 + nt * 8 + 2 * tt;
                *(uint*)(smb + r0 * 272 + C * 2) = h2pack(make_float2(
                    (acc[mt][nt][0] - mean[mt][0]) * rstd[mt][0],
                    (acc[mt][nt][1] - mean[mt][0]) * rstd[mt][0]));
                *(uint*)(smb + (r0 + 8) * 272 + C * 2) = h2pack(make_float2(
                    (acc[mt][nt][2] - mean[mt][1]) * rstd[mt][1],
                    (acc[mt][nt][3] - mean[mt][1]) * rstd[mt][1]));
            }
        }
    }
    __syncthreads();

    // ================= GEMM2: A via ldmatrix, B via __ldg =================
    #pragma unroll
    for (int mt = 0; mt < 2; mt++)
        #pragma unroll
        for (int nt = 0; nt < 4; nt++)
            #pragma unroll
            for (int z = 0; z < 4; z++) acc[mt][nt][z] = 0.0f;

    #pragma unroll
    for (int c = 0; c < NC2; c++) {
        #pragma unroll
        for (int ks = 0; ks < 2; ks++) {
            uint fa[2][4];
            #pragma unroll
            for (int mt = 0; mt < 2; mt++) {
                uint ad = smaddr(smb)
                        + (mh * 32 + mt * 16 + ldrow) * 272 + c * 64 + ks * 32 + ldcol;
                LDMX4(fa[mt], ad);
            }
            #pragma unroll
            for (int nt = 0; nt < 4; nt++) {
                uint2 bv = __ldg((const uint2*)g_B2 +
                                 c * 1024 + ((nh * 4 + nt) * 2 + ks) * 32 + lane);
                #pragma unroll
                for (int mt = 0; mt < 2; mt++)
                    mma16h(acc[mt][nt], fa[mt], bv.x, bv.y);
            }
        }
    }

    // ================= epilogue: direct fragment -> global stores =================
    #pragma unroll
    for (int nt = 0; nt < 4; nt++) {
        int C = nh * 32 + nt * 8 + 2 * tt;
        float2 bv = __ldg((const float2*)(g_pbfold + C));
        #pragma unroll
        for (int mt = 0; mt < 2; mt++) {
            int r0 = e0 + mh * 32 + mt * 16 + g;
            *(float2*)(out + (long long)r0 * EDIM + C) =
                make_float2(acc[mt][nt][0] + bv.x, acc[mt][nt][1] + bv.y);
            *(float2*)(out + (long long)(r0 + 8) * EDIM + C) =
                make_float2(acc[mt][nt][2] + bv.x, acc[mt][nt][3] + bv.y);
        }
    }
}

// ---------------- launch ----------------
extern "C" void kernel_launch(void* const* d_in, const int* in_sizes, int n_in,
                              void* d_out, int out_size) {
    const float* coords = (const float*)d_in[0];
    const float* mask   = (const float*)d_in[1];
    const int*   ri     = (const int*)d_in[2];
    const int*   ci     = (const int*)d_in[3];
    const float* wpw    = (const float*)d_in[4];
    const float* wpb    = (const float*)d_in[5];
    const float* wew    = (const float*)d_in[6];
    const float* lnw    = (const float*)d_in[7];
    const float* lnb    = (const float*)d_in[8];
    const float* pw     = (const float*)d_in[9];
    const float* pb     = (const float*)d_in[10];
    float* out = (float*)d_out;

    long long main_elems = (long long)NEDGE * EDIM;
    float* out_idx = ((long long)out_size > main_elems) ? (out + main_elems) : nullptr;

    cudaFuncSetAttribute(k_fused, cudaFuncAttributeMaxDynamicSharedMemorySize, SM_TOT);
    cudaFuncSetAttribute(k_topk,  cudaFuncAttributeMaxDynamicSharedMemorySize, TOPK_SMEM);

    k_init<<<100, 256>>>(coords, wew, pw, lnw, lnb, pb);
    k_topk<<<NRES / 4, 256, TOPK_SMEM>>>(mask, out_idx);
    k_fused<<<NEDGE / TILE, 256, SM_TOT>>>(ri, ci, wpw, wpb, out);
}